// round 6
// baseline (speedup 1.0000x reference)
#include <cuda_runtime.h>
#include <cstdint>

#define DM   1024
#define NH   16
#define DK   64
#define BATCH 2
#define SEQ  2048
#define MROWS (BATCH*SEQ)   // 4096
#define NW   (DM*DM)        // weight elems
#define NX   (MROWS*DM)     // activation elems
#define NHD  (BATCH*NH*SEQ*DK)

// Scratch (sanctioned __device__ globals; no allocation anywhere)
__device__ uint32_t g_Wh[4*NW];     // tf32 hi of Wq,Wk,Wv,Wo
__device__ uint32_t g_Wl[4*NW];     // tf32 lo
__device__ uint32_t g_Xt[3*NX];     // tf32 of Xq,Xk,Xv
__device__ uint32_t g_Qt[NHD];      // tf32 Q (prescaled), [b,h,s,d]
__device__ uint32_t g_Kt[NHD];
__device__ uint32_t g_Vt[NHD];
__device__ uint32_t g_Ct[NX];       // tf32 ctx, [b,s,h*d] concat

// ---------------------------------------------------------------------------
// helpers
// ---------------------------------------------------------------------------
__device__ __forceinline__ uint32_t f2tf(float f) {
    uint32_t u;
    asm("cvt.rna.tf32.f32 %0, %1;" : "=r"(u) : "f"(f));
    return u;
}
__device__ __forceinline__ float ex2f(float x) {
    float y;
    asm("ex2.approx.f32 %0, %1;" : "=f"(y) : "f"(x));
    return y;
}
__device__ __forceinline__ void mma_tf32(float* c, const uint32_t* a,
                                         uint32_t b0, uint32_t b1) {
    asm volatile(
        "mma.sync.aligned.m16n8k8.row.col.f32.tf32.tf32.f32 "
        "{%0,%1,%2,%3},{%4,%5,%6,%7},{%8,%9},{%0,%1,%2,%3};"
        : "+f"(c[0]), "+f"(c[1]), "+f"(c[2]), "+f"(c[3])
        : "r"(a[0]), "r"(a[1]), "r"(a[2]), "r"(a[3]), "r"(b0), "r"(b1));
}
__device__ __forceinline__ void cpa16(uint32_t dst, const void* src) {
    asm volatile("cp.async.cg.shared.global [%0], [%1], 16;\n"
                 :: "r"(dst), "l"(src));
}
#define CP_COMMIT() asm volatile("cp.async.commit_group;\n" ::: "memory")
#define CP_WAIT1()  asm volatile("cp.async.wait_group 1;\n" ::: "memory")

// ---------------------------------------------------------------------------
// prep: one-time conversions. z<4: weight z -> (hi,lo). z>=4: input -> tf32.
// ---------------------------------------------------------------------------
__global__ __launch_bounds__(256)
void prep(const float* __restrict__ Wq, const float* __restrict__ Wk,
          const float* __restrict__ Wv, const float* __restrict__ Wo,
          const float* __restrict__ Xq, const float* __restrict__ Xk,
          const float* __restrict__ Xv)
{
    const int z = blockIdx.z;
    const float* src = (z==0)?Wq:(z==1)?Wk:(z==2)?Wv:(z==3)?Wo:
                       (z==4)?Xq:(z==5)?Xk:Xv;
    const int n4 = ((z < 4) ? NW : NX) >> 2;
    const int stride = gridDim.x * blockDim.x;
    if (z < 4) {
        uint32_t* dh = g_Wh + z*NW;
        uint32_t* dl = g_Wl + z*NW;
        for (int i = blockIdx.x*blockDim.x + threadIdx.x; i < n4; i += stride) {
            float4 v = ((const float4*)src)[i];
            uint4 uh, ul;
            uh.x = f2tf(v.x); ul.x = f2tf(v.x - __uint_as_float(uh.x));
            uh.y = f2tf(v.y); ul.y = f2tf(v.y - __uint_as_float(uh.y));
            uh.z = f2tf(v.z); ul.z = f2tf(v.z - __uint_as_float(uh.z));
            uh.w = f2tf(v.w); ul.w = f2tf(v.w - __uint_as_float(uh.w));
            ((uint4*)dh)[i] = uh;
            ((uint4*)dl)[i] = ul;
        }
    } else {
        uint32_t* dt = g_Xt + (size_t)(z-4)*NX;
        for (int i = blockIdx.x*blockDim.x + threadIdx.x; i < n4; i += stride) {
            float4 v = ((const float4*)src)[i];
            uint4 u;
            u.x = f2tf(v.x); u.y = f2tf(v.y);
            u.z = f2tf(v.z); u.w = f2tf(v.w);
            ((uint4*)dt)[i] = u;
        }
    }
}

// ---------------------------------------------------------------------------
// GEMM on mma.sync tf32, pre-split W, cp.async double-buffered, K-chunk 32.
// Block 128m x 64n; 8 warps as 4m x 2n (warp 32x32). Pitch 36 (36%32=4 ->
// frag addr 4g+tg conflict-free; rows 144B = 16B multiple for cp.async).
// mode=1: z=blockIdx.z picks (Xq,Wq)->g_Qt (scaled), (Xk,Wk)->g_Kt, (Xv,Wv)->g_Vt
// mode=0: g_Ct x Wo -> out (fp32, +bias)
// ---------------------------------------------------------------------------
#define PA 36
#define GA_SZ (128*PA)      // 4608 words per A buffer
#define GW_SZ (64*PA)       // 2304 words per W buffer
#define GEMM_SMEM_WORDS (2*GA_SZ + 4*GW_SZ)       // 18432
#define GEMM_SMEM_BYTES (GEMM_SMEM_WORDS*4)       // 73728

__global__ __launch_bounds__(256, 2)
void gemm_mma(int mode, const float* __restrict__ b0p,
              const float* __restrict__ b1p, const float* __restrict__ b2p,
              float* __restrict__ outp)
{
    extern __shared__ uint32_t gsm[];
    uint32_t* AsB[2] = { gsm,            gsm + GA_SZ };
    uint32_t* WhB[2] = { gsm + 2*GA_SZ,  gsm + 2*GA_SZ + GW_SZ };
    uint32_t* WlB[2] = { gsm + 2*GA_SZ + 2*GW_SZ, gsm + 2*GA_SZ + 3*GW_SZ };

    const int z = blockIdx.z;
    const uint32_t* A = mode ? (g_Xt + (size_t)z*NX) : g_Ct;
    const int wsel = mode ? z : 3;
    const float* bias = mode ? ((z==0)?b0p:(z==1)?b1p:b2p) : b0p;
    const uint32_t* WhG = g_Wh + (size_t)wsel*NW;
    const uint32_t* WlG = g_Wl + (size_t)wsel*NW;

    const int m0 = blockIdx.y * 128;
    const int n0 = blockIdx.x * 64;
    const int tid = threadIdx.x;
    const int w = tid >> 5;
    const int lane = tid & 31;
    const int g = lane >> 2, tg = lane & 3;
    const int wm = w & 3;
    const int wn = w >> 2;

    const uint32_t sbase = (uint32_t)__cvta_generic_to_shared(gsm);

    // staging lambda: chunk kc (k-offset kc*32) into buffer b
    auto stage = [&](int kc, int b) {
        int k0 = kc * 32;
        uint32_t aB = sbase + ((b ? GA_SZ : 0) << 2);
#pragma unroll
        for (int i = 0; i < 4; i++) {        // A: 1024 segs, 4/thread
            int f = tid + i*256;
            int r = f >> 3, sgm = (f & 7) * 4;
            cpa16(aB + (r*PA + sgm)*4, A + (size_t)(m0 + r)*DM + k0 + sgm);
        }
        uint32_t hB = sbase + ((2*GA_SZ + (b ? GW_SZ : 0)) << 2);
        uint32_t lB = sbase + ((2*GA_SZ + 2*GW_SZ + (b ? GW_SZ : 0)) << 2);
#pragma unroll
        for (int i = 0; i < 2; i++) {        // Wh/Wl: 512 segs, 2/thread each
            int f = tid + i*256;
            int r = f >> 3, sgm = (f & 7) * 4;
            cpa16(hB + (r*PA + sgm)*4, WhG + (size_t)(n0 + r)*DM + k0 + sgm);
            cpa16(lB + (r*PA + sgm)*4, WlG + (size_t)(n0 + r)*DM + k0 + sgm);
        }
    };

    float acc[2][4][4];
#pragma unroll
    for (int mi = 0; mi < 2; mi++)
#pragma unroll
        for (int nt = 0; nt < 4; nt++)
#pragma unroll
            for (int j = 0; j < 4; j++) acc[mi][nt][j] = 0.f;

    stage(0, 0);
    CP_COMMIT();

    const int NC = DM/32;   // 32 chunks
    for (int kc = 0; kc < NC; kc++) {
        if (kc + 1 < NC) stage(kc + 1, (kc + 1) & 1);
        CP_COMMIT();        // possibly empty group; keeps wait-depth uniform
        CP_WAIT1();
        __syncthreads();

        uint32_t* As = AsB[kc & 1];
        uint32_t* Wh = WhB[kc & 1];
        uint32_t* Wl = WlB[kc & 1];
#pragma unroll
        for (int k8 = 0; k8 < 4; k8++) {
            uint32_t af[2][4];
#pragma unroll
            for (int mi = 0; mi < 2; mi++) {
                int ar = (wm*32 + mi*16 + g)*PA + k8*8 + tg;
                af[mi][0] = As[ar];
                af[mi][1] = As[ar + 8*PA];
                af[mi][2] = As[ar + 4];
                af[mi][3] = As[ar + 8*PA + 4];
            }
#pragma unroll
            for (int nt = 0; nt < 4; nt++) {
                int ka = (wn*32 + nt*8 + g)*PA + k8*8 + tg;
                uint32_t bh0 = Wh[ka], bh1 = Wh[ka + 4];
                uint32_t bl0 = Wl[ka], bl1 = Wl[ka + 4];
#pragma unroll
                for (int mi = 0; mi < 2; mi++) {
                    mma_tf32(acc[mi][nt], af[mi], bh0, bh1);
                    mma_tf32(acc[mi][nt], af[mi], bl0, bl1);
                }
            }
        }
        __syncthreads();
    }

    // epilogue
    const float QSCALE = 0.125f * 1.4426950408889634f;
    const int h = blockIdx.x;
    uint32_t* dstQKV = mode ? ((z==0) ? g_Qt : (z==1) ? g_Kt : g_Vt) : nullptr;
#pragma unroll
    for (int nt = 0; nt < 4; nt++) {
        int nc = wn*32 + nt*8 + 2*tg;
        float bb0 = bias[n0 + nc], bb1 = bias[n0 + nc + 1];
#pragma unroll
        for (int mi = 0; mi < 2; mi++) {
            int mA = m0 + wm*32 + mi*16 + g;
            int mB = mA + 8;
            float x0 = acc[mi][nt][0] + bb0, x1 = acc[mi][nt][1] + bb1;
            float y0 = acc[mi][nt][2] + bb0, y1 = acc[mi][nt][3] + bb1;
            if (mode) {
                if (z == 0) { x0 *= QSCALE; x1 *= QSCALE; y0 *= QSCALE; y1 *= QSCALE; }
                int bA = mA >> 11, sA = mA & (SEQ-1);
                int bB = mB >> 11, sB = mB & (SEQ-1);
                uint2 uA = make_uint2(f2tf(x0), f2tf(x1));
                uint2 uB = make_uint2(f2tf(y0), f2tf(y1));
                *(uint2*)&dstQKV[(((size_t)(bA*NH + h) * SEQ + sA) * DK) + nc] = uA;
                *(uint2*)&dstQKV[(((size_t)(bB*NH + h) * SEQ + sB) * DK) + nc] = uB;
            } else {
                *(float2*)&outp[(size_t)mA * DM + n0 + nc] = make_float2(x0, x1);
                *(float2*)&outp[(size_t)mB * DM + n0 + nc] = make_float2(y0, y1);
            }
        }
    }
}

// ---------------------------------------------------------------------------
// Flash attention, tf32 mma, v3: pre-converted operands, cp.async
// double-buffered K/V, P repacked C->A via shuffles (no smem roundtrip).
// smem: Qs 128x68 | Ks[2] 64x68 | Vs[2] 64x72 = 106496 B; 2 blocks/SM.
// ---------------------------------------------------------------------------
#define AQ_SZ (128*68)   // 8704
#define AK_SZ (64*68)    // 4352
#define AV_SZ (64*72)    // 4608
#define ATTN_SMEM_WORDS (AQ_SZ + 2*AK_SZ + 2*AV_SZ)   // 26624
#define ATTN_SMEM_BYTES (ATTN_SMEM_WORDS*4)           // 106496

__global__ __launch_bounds__(256, 2)
void attn_mma()
{
    extern __shared__ uint32_t sm[];
    uint32_t* Qs = sm;
    uint32_t* KsB[2] = { sm + AQ_SZ, sm + AQ_SZ + AK_SZ };
    uint32_t* VsB[2] = { sm + AQ_SZ + 2*AK_SZ, sm + AQ_SZ + 2*AK_SZ + AV_SZ };

    const int bh = blockIdx.y;
    const int q0 = blockIdx.x * 128;
    const size_t base = (size_t)bh * SEQ * DK;
    const int tid = threadIdx.x;
    const int w = tid >> 5;
    const int lane = tid & 31;
    const int g = lane >> 2, tg = lane & 3;

    const uint32_t sbase = (uint32_t)__cvta_generic_to_shared(sm);

    auto stageKV = [&](int t, int b) {
        int s0 = t * 64;
        uint32_t kB = sbase + ((AQ_SZ + (b ? AK_SZ : 0)) << 2);
        uint32_t vB = sbase + ((AQ_SZ + 2*AK_SZ + (b ? AV_SZ : 0)) << 2);
#pragma unroll
        for (int i = 0; i < 4; i++) {    // 1024 segs each, 4/thread
            int f = tid + i*256;
            int r = f >> 4, sgm = (f & 15) * 4;
            cpa16(kB + (r*68 + sgm)*4, g_Kt + base + (size_t)(s0 + r)*DK + sgm);
            cpa16(vB + (r*72 + sgm)*4, g_Vt + base + (size_t)(s0 + r)*DK + sgm);
        }
    };

    // prologue: Q + tile0 in one group
#pragma unroll
    for (int i = 0; i < 8; i++) {        // Q: 2048 segs, 8/thread
        int f = tid + i*256;
        int r = f >> 4, sgm = (f & 15) * 4;
        cpa16(sbase + ((r*68 + sgm) << 2),
              g_Qt + base + (size_t)(q0 + r)*DK + sgm);
    }
    stageKV(0, 0);
    CP_COMMIT();

    const int pr0 = (w*16 + g) * 68;
    const int pr1 = pr0 + 8 * 68;

    float of[8][4];
#pragma unroll
    for (int dt = 0; dt < 8; dt++)
#pragma unroll
        for (int j = 0; j < 4; j++) of[dt][j] = 0.f;
    float m0 = -1e30f, m1 = -1e30f, l0 = 0.f, l1 = 0.f;

    const int NT = SEQ/64;
    for (int t = 0; t < NT; t++) {
        if (t + 1 < NT) stageKV(t + 1, (t + 1) & 1);
        CP_COMMIT();
        CP_WAIT1();
        __syncthreads();

        uint32_t* Ks = KsB[t & 1];
        uint32_t* Vs = VsB[t & 1];

        // S = Q . K^T
        float sacc[8][4];
#pragma unroll
        for (int nt = 0; nt < 8; nt++)
#pragma unroll
            for (int j = 0; j < 4; j++) sacc[nt][j] = 0.f;
#pragma unroll
        for (int kt = 0; kt < 8; kt++) {
            uint32_t qf[4];
            int c = kt*8 + tg;
            qf[0] = Qs[pr0 + c];
            qf[1] = Qs[pr1 + c];
            qf[2] = Qs[pr0 + c + 4];
            qf[3] = Qs[pr1 + c + 4];
#pragma unroll
            for (int nt = 0; nt < 8; nt++) {
                int ka = (nt*8 + g)*68 + kt*8 + tg;
                mma_tf32(sacc[nt], qf, Ks[ka], Ks[ka + 4]);
            }
        }

        // online softmax (log2 domain; Q prescaled)
        float tm0 = -1e30f, tm1 = -1e30f;
#pragma unroll
        for (int nt = 0; nt < 8; nt++) {
            tm0 = fmaxf(tm0, fmaxf(sacc[nt][0], sacc[nt][1]));
            tm1 = fmaxf(tm1, fmaxf(sacc[nt][2], sacc[nt][3]));
        }
        tm0 = fmaxf(tm0, __shfl_xor_sync(0xffffffffu, tm0, 1));
        tm0 = fmaxf(tm0, __shfl_xor_sync(0xffffffffu, tm0, 2));
        tm1 = fmaxf(tm1, __shfl_xor_sync(0xffffffffu, tm1, 1));
        tm1 = fmaxf(tm1, __shfl_xor_sync(0xffffffffu, tm1, 2));

        float mn0 = fmaxf(m0, tm0), mn1 = fmaxf(m1, tm1);
        float a0 = ex2f(m0 - mn0), a1 = ex2f(m1 - mn1);
        m0 = mn0; m1 = mn1;

        float rs0 = 0.f, rs1 = 0.f;
#pragma unroll
        for (int nt = 0; nt < 8; nt++) {
            float p0 = ex2f(sacc[nt][0] - mn0);
            float p1 = ex2f(sacc[nt][1] - mn0);
            float p2 = ex2f(sacc[nt][2] - mn1);
            float p3 = ex2f(sacc[nt][3] - mn1);
            sacc[nt][0] = p0; sacc[nt][1] = p1;
            sacc[nt][2] = p2; sacc[nt][3] = p3;
            rs0 += p0 + p1;
            rs1 += p2 + p3;
        }
        rs0 += __shfl_xor_sync(0xffffffffu, rs0, 1);
        rs0 += __shfl_xor_sync(0xffffffffu, rs0, 2);
        rs1 += __shfl_xor_sync(0xffffffffu, rs1, 1);
        rs1 += __shfl_xor_sync(0xffffffffu, rs1, 2);
        l0 = l0 * a0 + rs0;
        l1 = l1 * a1 + rs1;
#pragma unroll
        for (int dt = 0; dt < 8; dt++) {
            of[dt][0] *= a0; of[dt][1] *= a0;
            of[dt][2] *= a1; of[dt][3] *= a1;
        }

        // O += P . V ; P repacked C-frag -> A-frag via shuffles
        const int lo = (g << 2) + (tg >> 1);
        const int hi = lo + 2;
        const bool odd = tg & 1;
#pragma unroll
        for (int kt = 0; kt < 8; kt++) {
            float v00 = __shfl_sync(0xffffffffu, sacc[kt][0], lo);
            float v01 = __shfl_sync(0xffffffffu, sacc[kt][1], lo);
            float v10 = __shfl_sync(0xffffffffu, sacc[kt][2], lo);
            float v11 = __shfl_sync(0xffffffffu, sacc[kt][3], lo);
            float v20 = __shfl_sync(0xffffffffu, sacc[kt][0], hi);
            float v21 = __shfl_sync(0xffffffffu, sacc[kt][1], hi);
            float v30 = __shfl_sync(0xffffffffu, sacc[kt][2], hi);
            float v31 = __shfl_sync(0xffffffffu, sacc[kt][3], hi);
            uint32_t pa[4];
            pa[0] = f2tf(odd ? v01 : v00);
            pa[1] = f2tf(odd ? v11 : v10);
            pa[2] = f2tf(odd ? v21 : v20);
            pa[3] = f2tf(odd ? v31 : v30);
            int vr0 = (kt*8 + tg)*72;
            int vr1 = vr0 + 4*72;
#pragma unroll
            for (int dt = 0; dt < 8; dt++) {
                mma_tf32(of[dt], pa, Vs[vr0 + dt*8 + g], Vs[vr1 + dt*8 + g]);
            }
        }
        __syncthreads();
    }

    // epilogue: normalize, write tf32 ctx in [b, s, h, d] concat layout
    float inv0 = 1.0f / l0, inv1 = 1.0f / l1;
    const int b = bh >> 4, h = bh & 15;
    const int sg0 = q0 + w*16 + g, sg1 = sg0 + 8;
#pragma unroll
    for (int dt = 0; dt < 8; dt++) {
        int d = dt*8 + 2*tg;
        uint2 u0 = make_uint2(f2tf(of[dt][0]*inv0), f2tf(of[dt][1]*inv0));
        uint2 u1 = make_uint2(f2tf(of[dt][2]*inv1), f2tf(of[dt][3]*inv1));
        *(uint2*)&g_Ct[((size_t)(b*SEQ + sg0) * NH + h) * DK + d] = u0;
        *(uint2*)&g_Ct[((size_t)(b*SEQ + sg1) * NH + h) * DK + d] = u1;
    }
}

// ---------------------------------------------------------------------------
extern "C" void kernel_launch(void* const* d_in, const int* in_sizes, int n_in,
                              void* d_out, int out_size)
{
    const float* Xq = (const float*)d_in[0];
    const float* Xk = (const float*)d_in[1];
    const float* Xv = (const float*)d_in[2];
    const float* Wq = (const float*)d_in[3];
    const float* bq = (const float*)d_in[4];
    const float* Wk = (const float*)d_in[5];
    const float* bk = (const float*)d_in[6];
    const float* Wv = (const float*)d_in[7];
    const float* bv = (const float*)d_in[8];
    const float* Wo = (const float*)d_in[9];
    const float* bo = (const float*)d_in[10];
    float* out = (float*)d_out;

    cudaFuncSetAttribute(gemm_mma,
                         cudaFuncAttributeMaxDynamicSharedMemorySize,
                         GEMM_SMEM_BYTES);
    cudaFuncSetAttribute(attn_mma,
                         cudaFuncAttributeMaxDynamicSharedMemorySize,
                         ATTN_SMEM_BYTES);

    dim3 blk(256);

    prep<<<dim3(1024, 1, 7), blk>>>(Wq, Wk, Wv, Wo, Xq, Xk, Xv);

    dim3 gq(DM/64, MROWS/128, 3);    // fused QKV
    gemm_mma<<<gq, blk, GEMM_SMEM_BYTES>>>(1, bq, bk, bv, nullptr);

    dim3 ga(SEQ/128, BATCH*NH);
    attn_mma<<<ga, blk, ATTN_SMEM_BYTES>>>();

    dim3 gp(DM/64, MROWS/128, 1);    // out projection
    gemm_mma<<<gp, blk, GEMM_SMEM_BYTES>>>(0, bo, bo, bo, out);
}

// round 7
// speedup vs baseline: 1.0999x; 1.0999x over previous
#include <cuda_runtime.h>
#include <cstdint>

#define DM   1024
#define NH   16
#define DK   64
#define BATCH 2
#define SEQ  2048
#define MROWS (BATCH*SEQ)   // 4096
#define NW   (DM*DM)        // weight elems
#define NX   (MROWS*DM)     // activation elems
#define NHD  (BATCH*NH*SEQ*DK)

// Scratch (sanctioned __device__ globals; no allocation anywhere)
__device__ uint32_t g_Wh[4*NW];     // tf32 hi of Wq,Wk,Wv,Wo
__device__ uint32_t g_Wl[4*NW];     // tf32 lo
__device__ uint32_t g_Xt[3*NX];     // tf32 of Xq,Xk,Xv
__device__ uint32_t g_Qt[NHD];      // tf32 Q (prescaled), [b,h,s,d]
__device__ uint32_t g_Kt[NHD];
__device__ uint32_t g_Vt[NHD];
__device__ uint32_t g_Ct[NX];       // tf32 ctx, [b,s,h*d] concat

// ---------------------------------------------------------------------------
// helpers
// ---------------------------------------------------------------------------
__device__ __forceinline__ uint32_t f2tf(float f) {
    uint32_t u;
    asm("cvt.rna.tf32.f32 %0, %1;" : "=r"(u) : "f"(f));
    return u;
}
__device__ __forceinline__ float ex2f(float x) {
    float y;
    asm("ex2.approx.f32 %0, %1;" : "=f"(y) : "f"(x));
    return y;
}
__device__ __forceinline__ void mma_tf32(float* c, const uint32_t* a,
                                         uint32_t b0, uint32_t b1) {
    asm volatile(
        "mma.sync.aligned.m16n8k8.row.col.f32.tf32.tf32.f32 "
        "{%0,%1,%2,%3},{%4,%5,%6,%7},{%8,%9},{%0,%1,%2,%3};"
        : "+f"(c[0]), "+f"(c[1]), "+f"(c[2]), "+f"(c[3])
        : "r"(a[0]), "r"(a[1]), "r"(a[2]), "r"(a[3]), "r"(b0), "r"(b1));
}
__device__ __forceinline__ void cpa16(uint32_t dst, const void* src) {
    asm volatile("cp.async.cg.shared.global [%0], [%1], 16;\n"
                 :: "r"(dst), "l"(src));
}
#define CP_COMMIT() asm volatile("cp.async.commit_group;\n" ::: "memory")
#define CP_WAIT1()  asm volatile("cp.async.wait_group 1;\n" ::: "memory")

// ---------------------------------------------------------------------------
// prep: one-time conversions. z<4: weight z -> (hi,lo). z>=4: input -> tf32.
// ---------------------------------------------------------------------------
__global__ __launch_bounds__(256)
void prep(const float* __restrict__ Wq, const float* __restrict__ Wk,
          const float* __restrict__ Wv, const float* __restrict__ Wo,
          const float* __restrict__ Xq, const float* __restrict__ Xk,
          const float* __restrict__ Xv)
{
    const int z = blockIdx.z;
    const float* src = (z==0)?Wq:(z==1)?Wk:(z==2)?Wv:(z==3)?Wo:
                       (z==4)?Xq:(z==5)?Xk:Xv;
    const int n4 = ((z < 4) ? NW : NX) >> 2;
    const int stride = gridDim.x * blockDim.x;
    if (z < 4) {
        uint32_t* dh = g_Wh + z*NW;
        uint32_t* dl = g_Wl + z*NW;
        for (int i = blockIdx.x*blockDim.x + threadIdx.x; i < n4; i += stride) {
            float4 v = ((const float4*)src)[i];
            uint4 uh, ul;
            uh.x = f2tf(v.x); ul.x = f2tf(v.x - __uint_as_float(uh.x));
            uh.y = f2tf(v.y); ul.y = f2tf(v.y - __uint_as_float(uh.y));
            uh.z = f2tf(v.z); ul.z = f2tf(v.z - __uint_as_float(uh.z));
            uh.w = f2tf(v.w); ul.w = f2tf(v.w - __uint_as_float(uh.w));
            ((uint4*)dh)[i] = uh;
            ((uint4*)dl)[i] = ul;
        }
    } else {
        uint32_t* dt = g_Xt + (size_t)(z-4)*NX;
        for (int i = blockIdx.x*blockDim.x + threadIdx.x; i < n4; i += stride) {
            float4 v = ((const float4*)src)[i];
            uint4 u;
            u.x = f2tf(v.x); u.y = f2tf(v.y);
            u.z = f2tf(v.z); u.w = f2tf(v.w);
            ((uint4*)dt)[i] = u;
        }
    }
}

// ---------------------------------------------------------------------------
// GEMM on mma.sync tf32, pre-split W, 3-stage cp.async pipeline, K-chunk 32,
// ONE __syncthreads per chunk (stage target (kc+2)%3 provably has no live
// readers past the iter-kc barrier). Prefetch distance = 2 chunks.
// Block 128m x 64n; 8 warps as 4m x 2n (warp 32x32); pitch 36.
// mode=1: z picks (Xq,Wq)->g_Qt (prescaled tf32), Xk->g_Kt, Xv->g_Vt
// mode=0: g_Ct x Wo -> out (fp32 + bias)
// ---------------------------------------------------------------------------
#define PA 36
#define GST_A  (128*PA)                 // 4608 words
#define GST_W  (64*PA)                  // 2304 words
#define GST_SZ (GST_A + 2*GST_W)        // 9216 words per stage
#define GEMM_SMEM_WORDS (3*GST_SZ)      // 27648
#define GEMM_SMEM_BYTES (GEMM_SMEM_WORDS*4)   // 110592

__global__ __launch_bounds__(256, 2)
void gemm_mma(int mode, const float* __restrict__ b0p,
              const float* __restrict__ b1p, const float* __restrict__ b2p,
              float* __restrict__ outp)
{
    extern __shared__ uint32_t gsm[];

    const int z = blockIdx.z;
    const uint32_t* A = mode ? (g_Xt + (size_t)z*NX) : g_Ct;
    const int wsel = mode ? z : 3;
    const float* bias = mode ? ((z==0)?b0p:(z==1)?b1p:b2p) : b0p;
    const uint32_t* WhG = g_Wh + (size_t)wsel*NW;
    const uint32_t* WlG = g_Wl + (size_t)wsel*NW;

    const int m0 = blockIdx.y * 128;
    const int n0 = blockIdx.x * 64;
    const int tid = threadIdx.x;
    const int w = tid >> 5;
    const int lane = tid & 31;
    const int g = lane >> 2, tg = lane & 3;
    const int wm = w & 3;
    const int wn = w >> 2;

    const uint32_t sbase = (uint32_t)__cvta_generic_to_shared(gsm);

    // stage chunk kc (k-offset kc*32) into stage buffer s
    auto stage = [&](int kc, int s) {
        int k0 = kc * 32;
        uint32_t aB = sbase + (uint32_t)(s * GST_SZ) * 4u;
#pragma unroll
        for (int i = 0; i < 4; i++) {        // A: 1024 segs, 4/thread
            int f = tid + i*256;
            int r = f >> 3, sg = (f & 7) * 4;
            cpa16(aB + (r*PA + sg)*4, A + (size_t)(m0 + r)*DM + k0 + sg);
        }
        uint32_t hB = aB + GST_A*4u;
        uint32_t lB = hB + GST_W*4u;
#pragma unroll
        for (int i = 0; i < 2; i++) {        // Wh/Wl: 512 segs, 2/thread each
            int f = tid + i*256;
            int r = f >> 3, sg = (f & 7) * 4;
            cpa16(hB + (r*PA + sg)*4, WhG + (size_t)(n0 + r)*DM + k0 + sg);
            cpa16(lB + (r*PA + sg)*4, WlG + (size_t)(n0 + r)*DM + k0 + sg);
        }
    };

    float acc[2][4][4];
#pragma unroll
    for (int mi = 0; mi < 2; mi++)
#pragma unroll
        for (int nt = 0; nt < 4; nt++)
#pragma unroll
            for (int j = 0; j < 4; j++) acc[mi][nt][j] = 0.f;

    stage(0, 0); CP_COMMIT();
    stage(1, 1); CP_COMMIT();

    const int NC = DM/32;   // 32 chunks
    int sb = 0;             // stage index of chunk kc
    for (int kc = 0; kc < NC; kc++) {
        CP_WAIT1();          // group kc complete (kc+1 may still fly)
        __syncthreads();     // make chunk kc visible to all warps

        uint32_t* As = gsm + sb * GST_SZ;
        uint32_t* Wh = As + GST_A;
        uint32_t* Wl = Wh + GST_W;
#pragma unroll
        for (int k8 = 0; k8 < 4; k8++) {
            uint32_t af[2][4];
#pragma unroll
            for (int mi = 0; mi < 2; mi++) {
                int ar = (wm*32 + mi*16 + g)*PA + k8*8 + tg;
                af[mi][0] = As[ar];
                af[mi][1] = As[ar + 8*PA];
                af[mi][2] = As[ar + 4];
                af[mi][3] = As[ar + 8*PA + 4];
            }
#pragma unroll
            for (int nt = 0; nt < 4; nt++) {
                int ka = (wn*32 + nt*8 + g)*PA + k8*8 + tg;
                uint32_t bh0 = Wh[ka], bh1 = Wh[ka + 4];
                uint32_t bl0 = Wl[ka], bl1 = Wl[ka + 4];
#pragma unroll
                for (int mi = 0; mi < 2; mi++) {
                    mma_tf32(acc[mi][nt], af[mi], bh0, bh1);
                    mma_tf32(acc[mi][nt], af[mi], bl0, bl1);
                }
            }
        }

        // prefetch chunk kc+2 into the buffer just freed (readers of it were
        // all done before this iteration's barrier)
        int s2 = sb + 2; if (s2 >= 3) s2 -= 3;
        if (kc + 2 < NC) stage(kc + 2, s2);
        CP_COMMIT();         // always commit (possibly empty) to keep depth uniform
        sb = (sb == 2) ? 0 : sb + 1;
    }

    // epilogue
    const float QSCALE = 0.125f * 1.4426950408889634f;
    const int h = blockIdx.x;
    uint32_t* dstQKV = mode ? ((z==0) ? g_Qt : (z==1) ? g_Kt : g_Vt) : nullptr;
#pragma unroll
    for (int nt = 0; nt < 4; nt++) {
        int nc = wn*32 + nt*8 + 2*tg;
        float bb0 = bias[n0 + nc], bb1 = bias[n0 + nc + 1];
#pragma unroll
        for (int mi = 0; mi < 2; mi++) {
            int mA = m0 + wm*32 + mi*16 + g;
            int mB = mA + 8;
            float x0 = acc[mi][nt][0] + bb0, x1 = acc[mi][nt][1] + bb1;
            float y0 = acc[mi][nt][2] + bb0, y1 = acc[mi][nt][3] + bb1;
            if (mode) {
                if (z == 0) { x0 *= QSCALE; x1 *= QSCALE; y0 *= QSCALE; y1 *= QSCALE; }
                int bA = mA >> 11, sA = mA & (SEQ-1);
                int bB = mB >> 11, sB = mB & (SEQ-1);
                uint2 uA = make_uint2(f2tf(x0), f2tf(x1));
                uint2 uB = make_uint2(f2tf(y0), f2tf(y1));
                *(uint2*)&dstQKV[(((size_t)(bA*NH + h) * SEQ + sA) * DK) + nc] = uA;
                *(uint2*)&dstQKV[(((size_t)(bB*NH + h) * SEQ + sB) * DK) + nc] = uB;
            } else {
                *(float2*)&outp[(size_t)mA * DM + n0 + nc] = make_float2(x0, x1);
                *(float2*)&outp[(size_t)mB * DM + n0 + nc] = make_float2(y0, y1);
            }
        }
    }
}

// ---------------------------------------------------------------------------
// Flash attention, tf32 mma (unchanged from R5): pre-converted operands,
// cp.async double-buffered K/V, P repacked C->A via shuffles.
// smem: Qs 128x68 | Ks[2] 64x68 | Vs[2] 64x72 = 106496 B; 2 blocks/SM.
// ---------------------------------------------------------------------------
#define AQ_SZ (128*68)   // 8704
#define AK_SZ (64*68)    // 4352
#define AV_SZ (64*72)    // 4608
#define ATTN_SMEM_WORDS (AQ_SZ + 2*AK_SZ + 2*AV_SZ)   // 26624
#define ATTN_SMEM_BYTES (ATTN_SMEM_WORDS*4)           // 106496

__global__ __launch_bounds__(256, 2)
void attn_mma()
{
    extern __shared__ uint32_t sm[];
    uint32_t* Qs = sm;
    uint32_t* KsB[2] = { sm + AQ_SZ, sm + AQ_SZ + AK_SZ };
    uint32_t* VsB[2] = { sm + AQ_SZ + 2*AK_SZ, sm + AQ_SZ + 2*AK_SZ + AV_SZ };

    const int bh = blockIdx.y;
    const int q0 = blockIdx.x * 128;
    const size_t base = (size_t)bh * SEQ * DK;
    const int tid = threadIdx.x;
    const int w = tid >> 5;
    const int lane = tid & 31;
    const int g = lane >> 2, tg = lane & 3;

    const uint32_t sbase = (uint32_t)__cvta_generic_to_shared(sm);

    auto stageKV = [&](int t, int b) {
        int s0 = t * 64;
        uint32_t kB = sbase + ((AQ_SZ + (b ? AK_SZ : 0)) << 2);
        uint32_t vB = sbase + ((AQ_SZ + 2*AK_SZ + (b ? AV_SZ : 0)) << 2);
#pragma unroll
        for (int i = 0; i < 4; i++) {
            int f = tid + i*256;
            int r = f >> 4, sg = (f & 15) * 4;
            cpa16(kB + (r*68 + sg)*4, g_Kt + base + (size_t)(s0 + r)*DK + sg);
            cpa16(vB + (r*72 + sg)*4, g_Vt + base + (size_t)(s0 + r)*DK + sg);
        }
    };

#pragma unroll
    for (int i = 0; i < 8; i++) {
        int f = tid + i*256;
        int r = f >> 4, sg = (f & 15) * 4;
        cpa16(sbase + ((r*68 + sg) << 2),
              g_Qt + base + (size_t)(q0 + r)*DK + sg);
    }
    stageKV(0, 0);
    CP_COMMIT();

    const int pr0 = (w*16 + g) * 68;
    const int pr1 = pr0 + 8 * 68;

    float of[8][4];
#pragma unroll
    for (int dt = 0; dt < 8; dt++)
#pragma unroll
        for (int j = 0; j < 4; j++) of[dt][j] = 0.f;
    float m0 = -1e30f, m1 = -1e30f, l0 = 0.f, l1 = 0.f;

    const int NT = SEQ/64;
    for (int t = 0; t < NT; t++) {
        if (t + 1 < NT) stageKV(t + 1, (t + 1) & 1);
        CP_COMMIT();
        CP_WAIT1();
        __syncthreads();

        uint32_t* Ks = KsB[t & 1];
        uint32_t* Vs = VsB[t & 1];

        float sacc[8][4];
#pragma unroll
        for (int nt = 0; nt < 8; nt++)
#pragma unroll
            for (int j = 0; j < 4; j++) sacc[nt][j] = 0.f;
#pragma unroll
        for (int kt = 0; kt < 8; kt++) {
            uint32_t qf[4];
            int c = kt*8 + tg;
            qf[0] = Qs[pr0 + c];
            qf[1] = Qs[pr1 + c];
            qf[2] = Qs[pr0 + c + 4];
            qf[3] = Qs[pr1 + c + 4];
#pragma unroll
            for (int nt = 0; nt < 8; nt++) {
                int ka = (nt*8 + g)*68 + kt*8 + tg;
                mma_tf32(sacc[nt], qf, Ks[ka], Ks[ka + 4]);
            }
        }

        float tm0 = -1e30f, tm1 = -1e30f;
#pragma unroll
        for (int nt = 0; nt < 8; nt++) {
            tm0 = fmaxf(tm0, fmaxf(sacc[nt][0], sacc[nt][1]));
            tm1 = fmaxf(tm1, fmaxf(sacc[nt][2], sacc[nt][3]));
        }
        tm0 = fmaxf(tm0, __shfl_xor_sync(0xffffffffu, tm0, 1));
        tm0 = fmaxf(tm0, __shfl_xor_sync(0xffffffffu, tm0, 2));
        tm1 = fmaxf(tm1, __shfl_xor_sync(0xffffffffu, tm1, 1));
        tm1 = fmaxf(tm1, __shfl_xor_sync(0xffffffffu, tm1, 2));

        float mn0 = fmaxf(m0, tm0), mn1 = fmaxf(m1, tm1);
        float a0 = ex2f(m0 - mn0), a1 = ex2f(m1 - mn1);
        m0 = mn0; m1 = mn1;

        float rs0 = 0.f, rs1 = 0.f;
#pragma unroll
        for (int nt = 0; nt < 8; nt++) {
            float p0 = ex2f(sacc[nt][0] - mn0);
            float p1 = ex2f(sacc[nt][1] - mn0);
            float p2 = ex2f(sacc[nt][2] - mn1);
            float p3 = ex2f(sacc[nt][3] - mn1);
            sacc[nt][0] = p0; sacc[nt][1] = p1;
            sacc[nt][2] = p2; sacc[nt][3] = p3;
            rs0 += p0 + p1;
            rs1 += p2 + p3;
        }
        rs0 += __shfl_xor_sync(0xffffffffu, rs0, 1);
        rs0 += __shfl_xor_sync(0xffffffffu, rs0, 2);
        rs1 += __shfl_xor_sync(0xffffffffu, rs1, 1);
        rs1 += __shfl_xor_sync(0xffffffffu, rs1, 2);
        l0 = l0 * a0 + rs0;
        l1 = l1 * a1 + rs1;
#pragma unroll
        for (int dt = 0; dt < 8; dt++) {
            of[dt][0] *= a0; of[dt][1] *= a0;
            of[dt][2] *= a1; of[dt][3] *= a1;
        }

        const int lo = (g << 2) + (tg >> 1);
        const int hi = lo + 2;
        const bool odd = tg & 1;
#pragma unroll
        for (int kt = 0; kt < 8; kt++) {
            float v00 = __shfl_sync(0xffffffffu, sacc[kt][0], lo);
            float v01 = __shfl_sync(0xffffffffu, sacc[kt][1], lo);
            float v10 = __shfl_sync(0xffffffffu, sacc[kt][2], lo);
            float v11 = __shfl_sync(0xffffffffu, sacc[kt][3], lo);
            float v20 = __shfl_sync(0xffffffffu, sacc[kt][0], hi);
            float v21 = __shfl_sync(0xffffffffu, sacc[kt][1], hi);
            float v30 = __shfl_sync(0xffffffffu, sacc[kt][2], hi);
            float v31 = __shfl_sync(0xffffffffu, sacc[kt][3], hi);
            uint32_t pa[4];
            pa[0] = f2tf(odd ? v01 : v00);
            pa[1] = f2tf(odd ? v11 : v10);
            pa[2] = f2tf(odd ? v21 : v20);
            pa[3] = f2tf(odd ? v31 : v30);
            int vr0 = (kt*8 + tg)*72;
            int vr1 = vr0 + 4*72;
#pragma unroll
            for (int dt = 0; dt < 8; dt++) {
                mma_tf32(of[dt], pa, Vs[vr0 + dt*8 + g], Vs[vr1 + dt*8 + g]);
            }
        }
        __syncthreads();
    }

    float inv0 = 1.0f / l0, inv1 = 1.0f / l1;
    const int b = bh >> 4, h = bh & 15;
    const int sg0 = q0 + w*16 + g, sg1 = sg0 + 8;
#pragma unroll
    for (int dt = 0; dt < 8; dt++) {
        int d = dt*8 + 2*tg;
        uint2 u0 = make_uint2(f2tf(of[dt][0]*inv0), f2tf(of[dt][1]*inv0));
        uint2 u1 = make_uint2(f2tf(of[dt][2]*inv1), f2tf(of[dt][3]*inv1));
        *(uint2*)&g_Ct[((size_t)(b*SEQ + sg0) * NH + h) * DK + d] = u0;
        *(uint2*)&g_Ct[((size_t)(b*SEQ + sg1) * NH + h) * DK + d] = u1;
    }
}

// ---------------------------------------------------------------------------
extern "C" void kernel_launch(void* const* d_in, const int* in_sizes, int n_in,
                              void* d_out, int out_size)
{
    const float* Xq = (const float*)d_in[0];
    const float* Xk = (const float*)d_in[1];
    const float* Xv = (const float*)d_in[2];
    const float* Wq = (const float*)d_in[3];
    const float* bq = (const float*)d_in[4];
    const float* Wk = (const float*)d_in[5];
    const float* bk = (const float*)d_in[6];
    const float* Wv = (const float*)d_in[7];
    const float* bv = (const float*)d_in[8];
    const float* Wo = (const float*)d_in[9];
    const float* bo = (const float*)d_in[10];
    float* out = (float*)d_out;

    cudaFuncSetAttribute(gemm_mma,
                         cudaFuncAttributeMaxDynamicSharedMemorySize,
                         GEMM_SMEM_BYTES);
    cudaFuncSetAttribute(attn_mma,
                         cudaFuncAttributeMaxDynamicSharedMemorySize,
                         ATTN_SMEM_BYTES);

    dim3 blk(256);

    prep<<<dim3(1024, 1, 7), blk>>>(Wq, Wk, Wv, Wo, Xq, Xk, Xv);

    dim3 gq(DM/64, MROWS/128, 3);    // fused QKV
    gemm_mma<<<gq, blk, GEMM_SMEM_BYTES>>>(1, bq, bk, bv, nullptr);

    dim3 ga(SEQ/128, BATCH*NH);
    attn_mma<<<ga, blk, ATTN_SMEM_BYTES>>>();

    dim3 gp(DM/64, MROWS/128, 1);    // out projection
    gemm_mma<<<gp, blk, GEMM_SMEM_BYTES>>>(0, bo, bo, bo, out);
}

// round 9
// speedup vs baseline: 1.2390x; 1.1265x over previous
#include <cuda_runtime.h>
#include <cuda_bf16.h>
#include <cstdint>

#define DM   1024
#define NH   16
#define DK   64
#define BATCH 2
#define SEQ  2048
#define MROWS (BATCH*SEQ)   // 4096
#define NW   (DM*DM)
#define NX   (MROWS*DM)
#define NHD  (BATCH*NH*SEQ*DK)

// Scratch (sanctioned __device__ globals)
__device__ __nv_bfloat16 g_Whi[4*NW], g_Wlo[4*NW];   // bf16 split weights
__device__ __nv_bfloat16 g_Xhi[3*NX], g_Xlo[3*NX];   // bf16 split inputs
__device__ __nv_bfloat16 g_Chi[NX],   g_Clo[NX];     // bf16 split ctx
__device__ uint32_t g_Qt[NHD];                        // tf32 Q (prescaled) [b,h,s,d]
__device__ uint32_t g_Kt[NHD];
__device__ uint32_t g_Vt[NHD];

// ---------------------------------------------------------------------------
// helpers
// ---------------------------------------------------------------------------
__device__ __forceinline__ uint32_t f2tf(float f) {
    uint32_t u;
    asm("cvt.rna.tf32.f32 %0, %1;" : "=r"(u) : "f"(f));
    return u;
}
__device__ __forceinline__ float ex2f(float x) {
    float y;
    asm("ex2.approx.f32 %0, %1;" : "=f"(y) : "f"(x));
    return y;
}
__device__ __forceinline__ void mma_tf32(float* c, const uint32_t* a,
                                         uint32_t b0, uint32_t b1) {
    asm volatile(
        "mma.sync.aligned.m16n8k8.row.col.f32.tf32.tf32.f32 "
        "{%0,%1,%2,%3},{%4,%5,%6,%7},{%8,%9},{%0,%1,%2,%3};"
        : "+f"(c[0]), "+f"(c[1]), "+f"(c[2]), "+f"(c[3])
        : "r"(a[0]), "r"(a[1]), "r"(a[2]), "r"(a[3]), "r"(b0), "r"(b1));
}
// bf16 m16n8k16 (full-rate HMMA): A 4 regs (bf16x2), B 2 regs, C 4 f32
__device__ __forceinline__ void mma_bf16(float* c, const uint32_t* a,
                                         uint32_t b0, uint32_t b1) {
    asm volatile(
        "mma.sync.aligned.m16n8k16.row.col.f32.bf16.bf16.f32 "
        "{%0,%1,%2,%3},{%4,%5,%6,%7},{%8,%9},{%0,%1,%2,%3};"
        : "+f"(c[0]), "+f"(c[1]), "+f"(c[2]), "+f"(c[3])
        : "r"(a[0]), "r"(a[1]), "r"(a[2]), "r"(a[3]), "r"(b0), "r"(b1));
}
__device__ __forceinline__ void cpa16(uint32_t dst, const void* src) {
    asm volatile("cp.async.cg.shared.global [%0], [%1], 16;\n"
                 :: "r"(dst), "l"(src));
}
#define CP_COMMIT() asm volatile("cp.async.commit_group;\n" ::: "memory")
#define CP_WAIT1()  asm volatile("cp.async.wait_group 1;\n" ::: "memory")

// ---------------------------------------------------------------------------
// prep: one-time bf16 hi/lo splits. z 0-3: weights; z 4-6: inputs.
// ---------------------------------------------------------------------------
__global__ __launch_bounds__(256)
void prep(const float* __restrict__ Wq, const float* __restrict__ Wk,
          const float* __restrict__ Wv, const float* __restrict__ Wo,
          const float* __restrict__ Xq, const float* __restrict__ Xk,
          const float* __restrict__ Xv)
{
    const int z = blockIdx.z;
    const float* src = (z==0)?Wq:(z==1)?Wk:(z==2)?Wv:(z==3)?Wo:
                       (z==4)?Xq:(z==5)?Xk:Xv;
    __nv_bfloat16* dh = (z < 4) ? (g_Whi + (size_t)z*NW)
                                : (g_Xhi + (size_t)(z-4)*NX);
    __nv_bfloat16* dl = (z < 4) ? (g_Wlo + (size_t)z*NW)
                                : (g_Xlo + (size_t)(z-4)*NX);
    const int n4 = ((z < 4) ? NW : NX) >> 2;
    const int stride = gridDim.x * blockDim.x;
    for (int i = blockIdx.x*blockDim.x + threadIdx.x; i < n4; i += stride) {
        float4 v = ((const float4*)src)[i];
        __nv_bfloat16 h0 = __float2bfloat16(v.x);
        __nv_bfloat16 h1 = __float2bfloat16(v.y);
        __nv_bfloat16 h2 = __float2bfloat16(v.z);
        __nv_bfloat16 h3 = __float2bfloat16(v.w);
        __nv_bfloat16 l0 = __float2bfloat16(v.x - __bfloat162float(h0));
        __nv_bfloat16 l1 = __float2bfloat16(v.y - __bfloat162float(h1));
        __nv_bfloat16 l2 = __float2bfloat16(v.z - __bfloat162float(h2));
        __nv_bfloat16 l3 = __float2bfloat16(v.w - __bfloat162float(h3));
        uint32_t ph0 = ((uint32_t)__bfloat16_as_ushort(h1) << 16) | __bfloat16_as_ushort(h0);
        uint32_t ph1 = ((uint32_t)__bfloat16_as_ushort(h3) << 16) | __bfloat16_as_ushort(h2);
        uint32_t pl0 = ((uint32_t)__bfloat16_as_ushort(l1) << 16) | __bfloat16_as_ushort(l0);
        uint32_t pl1 = ((uint32_t)__bfloat16_as_ushort(l3) << 16) | __bfloat16_as_ushort(l2);
        ((uint2*)dh)[i] = make_uint2(ph0, ph1);
        ((uint2*)dl)[i] = make_uint2(pl0, pl1);
    }
}

// ---------------------------------------------------------------------------
// GEMM on mma.sync bf16 m16n8k16, both operands hi/lo split, 3 products
// (AhWh + AlWh + AhWl) into one fp32 accumulator.
// Block 128m x 64n, K-chunk 64 (= 4 k16 slabs), 2-stage cp.async, 2 syncs
// per chunk. 8 warps as 4m x 2n (warp tile 32x32). Pitch 36 u32 (=bf16x2
// pairs: 32 data + 4 pad) -> same conflict-free fragment addressing as tf32.
// mode=1: z picks (Xq,Wq)->g_Qt (prescaled tf32), Xk->g_Kt, Xv->g_Vt
// mode=0: (ctx_hi/lo, Wo) -> out fp32 + bias
// ---------------------------------------------------------------------------
#define PB 36
#define S_A (128*PB)                  // 4608 words per A operand
#define S_W (64*PB)                   // 2304 words per W operand
#define STG_WORDS (2*S_A + 2*S_W)     // 13824 (Ahi, Alo, Whi, Wlo)
#define AH_O 0
#define AL_O S_A
#define WH_O (2*S_A)
#define WL_O (2*S_A + S_W)
#define GEMM_SMEM_WORDS (2*STG_WORDS)       // 27648
#define GEMM_SMEM_BYTES (GEMM_SMEM_WORDS*4) // 110592

__global__ __launch_bounds__(256, 2)
void gemm_bf16(int mode, const float* __restrict__ b0p,
               const float* __restrict__ b1p, const float* __restrict__ b2p,
               float* __restrict__ outp)
{
    extern __shared__ uint32_t gsm[];

    const int z = blockIdx.z;
    const __nv_bfloat16* Ahi = mode ? (g_Xhi + (size_t)z*NX) : g_Chi;
    const __nv_bfloat16* Alo = mode ? (g_Xlo + (size_t)z*NX) : g_Clo;
    const int wsel = mode ? z : 3;
    const __nv_bfloat16* WhiG = g_Whi + (size_t)wsel*NW;
    const __nv_bfloat16* WloG = g_Wlo + (size_t)wsel*NW;
    const float* bias = mode ? ((z==0)?b0p:(z==1)?b1p:b2p) : b0p;

    const int m0 = blockIdx.y * 128;
    const int n0 = blockIdx.x * 64;
    const int tid = threadIdx.x;
    const int w = tid >> 5;
    const int lane = tid & 31;
    const int g = lane >> 2, tg = lane & 3;
    const int wm = w & 3;
    const int wn = w >> 2;

    const uint32_t sbase = (uint32_t)__cvta_generic_to_shared(gsm);

    // stage chunk kc (k-offset kc*64 bf16 elems) into stage buffer s
    auto stage = [&](int kc, int s) {
        int k0 = kc * 64;
        uint32_t bb = sbase + (uint32_t)(s * STG_WORDS) * 4u;
        // A hi/lo: 1024 16B-granules each (128 rows x 8), 4 per thread
#pragma unroll
        for (int i = 0; i < 4; i++) {
            int f = tid + i*256;
            int r = f >> 3, ch = f & 7;
            uint32_t d = bb + (uint32_t)(r*PB + ch*4)*4u;
            size_t so = (size_t)(m0 + r)*DM + k0 + ch*8;
            cpa16(d + AH_O*4u, Ahi + so);
            cpa16(d + AL_O*4u, Alo + so);
        }
        // W hi/lo: 512 granules each (64 rows x 8), 2 per thread
#pragma unroll
        for (int i = 0; i < 2; i++) {
            int f = tid + i*256;
            int r = f >> 3, ch = f & 7;
            uint32_t d = bb + (uint32_t)(r*PB + ch*4)*4u;
            size_t so = (size_t)(n0 + r)*DM + k0 + ch*8;
            cpa16(d + WH_O*4u, WhiG + so);
            cpa16(d + WL_O*4u, WloG + so);
        }
    };

    float acc[2][4][4];
#pragma unroll
    for (int mi = 0; mi < 2; mi++)
#pragma unroll
        for (int nt = 0; nt < 4; nt++)
#pragma unroll
            for (int j = 0; j < 4; j++) acc[mi][nt][j] = 0.f;

    stage(0, 0); CP_COMMIT();
    stage(1, 1); CP_COMMIT();

    const int NCH = DM/64;   // 16 chunks
    for (int kc = 0; kc < NCH; kc++) {
        CP_WAIT1();          // chunk kc's group complete (kc+1 may still fly)
        __syncthreads();

        uint32_t* Sh = gsm + (kc & 1) * STG_WORDS;
        uint32_t* Ah = Sh + AH_O;
        uint32_t* Al = Sh + AL_O;
        uint32_t* Wh = Sh + WH_O;
        uint32_t* Wl = Sh + WL_O;

#pragma unroll
        for (int ks = 0; ks < 4; ks++) {     // 4 k16 slabs
            int c = ks*8 + tg;               // pair-column
            uint32_t afh[2][4], afl[2][4];
#pragma unroll
            for (int mi = 0; mi < 2; mi++) {
                int ar = (wm*32 + mi*16 + g)*PB + c;
                afh[mi][0] = Ah[ar];
                afh[mi][1] = Ah[ar + 8*PB];
                afh[mi][2] = Ah[ar + 4];
                afh[mi][3] = Ah[ar + 8*PB + 4];
                afl[mi][0] = Al[ar];
                afl[mi][1] = Al[ar + 8*PB];
                afl[mi][2] = Al[ar + 4];
                afl[mi][3] = Al[ar + 8*PB + 4];
            }
#pragma unroll
            for (int nt = 0; nt < 4; nt++) {
                int ka = (wn*32 + nt*8 + g)*PB + c;
                uint32_t bh0 = Wh[ka], bh1 = Wh[ka + 4];
                uint32_t bl0 = Wl[ka], bl1 = Wl[ka + 4];
#pragma unroll
                for (int mi = 0; mi < 2; mi++) {
                    mma_bf16(acc[mi][nt], afh[mi], bh0, bh1);
                    mma_bf16(acc[mi][nt], afl[mi], bh0, bh1);
                    mma_bf16(acc[mi][nt], afh[mi], bl0, bl1);
                }
            }
        }
        __syncthreads();     // all warps done reading buffer kc&1

        if (kc + 2 < NCH) stage(kc + 2, kc & 1);
        CP_COMMIT();         // uniform group depth (possibly empty)
    }

    // epilogue
    const float QSCALE = 0.125f * 1.4426950408889634f;
    const int h = blockIdx.x;
    uint32_t* dstQKV = mode ? ((z==0) ? g_Qt : (z==1) ? g_Kt : g_Vt) : nullptr;
#pragma unroll
    for (int nt = 0; nt < 4; nt++) {
        int nc = wn*32 + nt*8 + 2*tg;
        float bb0 = bias[n0 + nc], bb1 = bias[n0 + nc + 1];
#pragma unroll
        for (int mi = 0; mi < 2; mi++) {
            int mA = m0 + wm*32 + mi*16 + g;
            int mB = mA + 8;
            float x0 = acc[mi][nt][0] + bb0, x1 = acc[mi][nt][1] + bb1;
            float y0 = acc[mi][nt][2] + bb0, y1 = acc[mi][nt][3] + bb1;
            if (mode) {
                if (z == 0) { x0 *= QSCALE; x1 *= QSCALE; y0 *= QSCALE; y1 *= QSCALE; }
                int bA = mA >> 11, sA = mA & (SEQ-1);
                int bB = mB >> 11, sB = mB & (SEQ-1);
                uint2 uA = make_uint2(f2tf(x0), f2tf(x1));
                uint2 uB = make_uint2(f2tf(y0), f2tf(y1));
                *(uint2*)&dstQKV[(((size_t)(bA*NH + h) * SEQ + sA) * DK) + nc] = uA;
                *(uint2*)&dstQKV[(((size_t)(bB*NH + h) * SEQ + sB) * DK) + nc] = uB;
            } else {
                *(float2*)&outp[(size_t)mA * DM + n0 + nc] = make_float2(x0, x1);
                *(float2*)&outp[(size_t)mB * DM + n0 + nc] = make_float2(y0, y1);
            }
        }
    }
}

// ---------------------------------------------------------------------------
// Flash attention, tf32 mma.sync (R6 structure): cp.async double-buffered
// K/V, P repacked C->A via shuffles. Epilogue writes bf16 hi/lo ctx.
// ---------------------------------------------------------------------------
#define AQ_SZ (128*68)
#define AK_SZ (64*68)
#define AV_SZ (64*72)
#define ATTN_SMEM_WORDS (AQ_SZ + 2*AK_SZ + 2*AV_SZ)
#define ATTN_SMEM_BYTES (ATTN_SMEM_WORDS*4)           // 106496

__global__ __launch_bounds__(256, 2)
void attn_mma()
{
    extern __shared__ uint32_t sm[];
    uint32_t* Qs = sm;
    uint32_t* KsB[2] = { sm + AQ_SZ, sm + AQ_SZ + AK_SZ };
    uint32_t* VsB[2] = { sm + AQ_SZ + 2*AK_SZ, sm + AQ_SZ + 2*AK_SZ + AV_SZ };

    const int bh = blockIdx.y;
    const int q0 = blockIdx.x * 128;
    const size_t base = (size_t)bh * SEQ * DK;
    const int tid = threadIdx.x;
    const int w = tid >> 5;
    const int lane = tid & 31;
    const int g = lane >> 2, tg = lane & 3;

    const uint32_t sbase = (uint32_t)__cvta_generic_to_shared(sm);

    auto stageKV = [&](int t, int b) {
        int s0 = t * 64;
        uint32_t kB = sbase + ((AQ_SZ + (b ? AK_SZ : 0)) << 2);
        uint32_t vB = sbase + ((AQ_SZ + 2*AK_SZ + (b ? AV_SZ : 0)) << 2);
#pragma unroll
        for (int i = 0; i < 4; i++) {
            int f = tid + i*256;
            int r = f >> 4, sg = (f & 15) * 4;
            cpa16(kB + (r*68 + sg)*4, g_Kt + base + (size_t)(s0 + r)*DK + sg);
            cpa16(vB + (r*72 + sg)*4, g_Vt + base + (size_t)(s0 + r)*DK + sg);
        }
    };

#pragma unroll
    for (int i = 0; i < 8; i++) {
        int f = tid + i*256;
        int r = f >> 4, sg = (f & 15) * 4;
        cpa16(sbase + ((r*68 + sg) << 2),
              g_Qt + base + (size_t)(q0 + r)*DK + sg);
    }
    stageKV(0, 0);
    CP_COMMIT();

    const int pr0 = (w*16 + g) * 68;
    const int pr1 = pr0 + 8 * 68;

    float of[8][4];
#pragma unroll
    for (int dt = 0; dt < 8; dt++)
#pragma unroll
        for (int j = 0; j < 4; j++) of[dt][j] = 0.f;
    float m0 = -1e30f, m1 = -1e30f, l0 = 0.f, l1 = 0.f;

    const int NT = SEQ/64;
    for (int t = 0; t < NT; t++) {
        if (t + 1 < NT) stageKV(t + 1, (t + 1) & 1);
        CP_COMMIT();
        CP_WAIT1();
        __syncthreads();

        uint32_t* Ks = KsB[t & 1];
        uint32_t* Vs = VsB[t & 1];

        float sacc[8][4];
#pragma unroll
        for (int nt = 0; nt < 8; nt++)
#pragma unroll
            for (int j = 0; j < 4; j++) sacc[nt][j] = 0.f;
#pragma unroll
        for (int kt = 0; kt < 8; kt++) {
            uint32_t qf[4];
            int c = kt*8 + tg;
            qf[0] = Qs[pr0 + c];
            qf[1] = Qs[pr1 + c];
            qf[2] = Qs[pr0 + c + 4];
            qf[3] = Qs[pr1 + c + 4];
#pragma unroll
            for (int nt = 0; nt < 8; nt++) {
                int ka = (nt*8 + g)*68 + kt*8 + tg;
                mma_tf32(sacc[nt], qf, Ks[ka], Ks[ka + 4]);
            }
        }

        float tm0 = -1e30f, tm1 = -1e30f;
#pragma unroll
        for (int nt = 0; nt < 8; nt++) {
            tm0 = fmaxf(tm0, fmaxf(sacc[nt][0], sacc[nt][1]));
            tm1 = fmaxf(tm1, fmaxf(sacc[nt][2], sacc[nt][3]));
        }
        tm0 = fmaxf(tm0, __shfl_xor_sync(0xffffffffu, tm0, 1));
        tm0 = fmaxf(tm0, __shfl_xor_sync(0xffffffffu, tm0, 2));
        tm1 = fmaxf(tm1, __shfl_xor_sync(0xffffffffu, tm1, 1));
        tm1 = fmaxf(tm1, __shfl_xor_sync(0xffffffffu, tm1, 2));

        float mn0 = fmaxf(m0, tm0), mn1 = fmaxf(m1, tm1);
        float a0 = ex2f(m0 - mn0), a1 = ex2f(m1 - mn1);
        m0 = mn0; m1 = mn1;

        float rs0 = 0.f, rs1 = 0.f;
#pragma unroll
        for (int nt = 0; nt < 8; nt++) {
            float p0 = ex2f(sacc[nt][0] - mn0);
            float p1 = ex2f(sacc[nt][1] - mn0);
            float p2 = ex2f(sacc[nt][2] - mn1);
            float p3 = ex2f(sacc[nt][3] - mn1);
            sacc[nt][0] = p0; sacc[nt][1] = p1;
            sacc[nt][2] = p2; sacc[nt][3] = p3;
            rs0 += p0 + p1;
            rs1 += p2 + p3;
        }
        rs0 += __shfl_xor_sync(0xffffffffu, rs0, 1);
        rs0 += __shfl_xor_sync(0xffffffffu, rs0, 2);
        rs1 += __shfl_xor_sync(0xffffffffu, rs1, 1);
        rs1 += __shfl_xor_sync(0xffffffffu, rs1, 2);
        l0 = l0 * a0 + rs0;
        l1 = l1 * a1 + rs1;
#pragma unroll
        for (int dt = 0; dt < 8; dt++) {
            of[dt][0] *= a0; of[dt][1] *= a0;
            of[dt][2] *= a1; of[dt][3] *= a1;
        }

        const int lo = (g << 2) + (tg >> 1);
        const int hi = lo + 2;
        const bool odd = tg & 1;
#pragma unroll
        for (int kt = 0; kt < 8; kt++) {
            float v00 = __shfl_sync(0xffffffffu, sacc[kt][0], lo);
            float v01 = __shfl_sync(0xffffffffu, sacc[kt][1], lo);
            float v10 = __shfl_sync(0xffffffffu, sacc[kt][2], lo);
            float v11 = __shfl_sync(0xffffffffu, sacc[kt][3], lo);
            float v20 = __shfl_sync(0xffffffffu, sacc[kt][0], hi);
            float v21 = __shfl_sync(0xffffffffu, sacc[kt][1], hi);
            float v30 = __shfl_sync(0xffffffffu, sacc[kt][2], hi);
            float v31 = __shfl_sync(0xffffffffu, sacc[kt][3], hi);
            uint32_t pa[4];
            pa[0] = f2tf(odd ? v01 : v00);
            pa[1] = f2tf(odd ? v11 : v10);
            pa[2] = f2tf(odd ? v21 : v20);
            pa[3] = f2tf(odd ? v31 : v30);
            int vr0 = (kt*8 + tg)*72;
            int vr1 = vr0 + 4*72;
#pragma unroll
            for (int dt = 0; dt < 8; dt++) {
                mma_tf32(of[dt], pa, Vs[vr0 + dt*8 + g], Vs[vr1 + dt*8 + g]);
            }
        }
        __syncthreads();
    }

    // epilogue: normalize -> bf16 hi/lo ctx, [b, s, h, d] concat layout
    float inv0 = 1.0f / l0, inv1 = 1.0f / l1;
    const int b = bh >> 4, h = bh & 15;
    const int sg0 = q0 + w*16 + g, sg1 = sg0 + 8;
#pragma unroll
    for (int dt = 0; dt < 8; dt++) {
        int dcol = dt*8 + 2*tg;
        size_t i0 = ((size_t)(b*SEQ + sg0) * NH + h) * DK + dcol;
        size_t i1 = ((size_t)(b*SEQ + sg1) * NH + h) * DK + dcol;
        float x0 = of[dt][0]*inv0, x1 = of[dt][1]*inv0;
        float y0 = of[dt][2]*inv1, y1 = of[dt][3]*inv1;
        __nv_bfloat16 hx0 = __float2bfloat16(x0);
        __nv_bfloat16 hx1 = __float2bfloat16(x1);
        __nv_bfloat16 hy0 = __float2bfloat16(y0);
        __nv_bfloat16 hy1 = __float2bfloat16(y1);
        __nv_bfloat16 lx0 = __float2bfloat16(x0 - __bfloat162float(hx0));
        __nv_bfloat16 lx1 = __float2bfloat16(x1 - __bfloat162float(hx1));
        __nv_bfloat16 ly0 = __float2bfloat16(y0 - __bfloat162float(hy0));
        __nv_bfloat16 ly1 = __float2bfloat16(y1 - __bfloat162float(hy1));
        *(uint32_t*)&g_Chi[i0] = ((uint32_t)__bfloat16_as_ushort(hx1) << 16) | __bfloat16_as_ushort(hx0);
        *(uint32_t*)&g_Clo[i0] = ((uint32_t)__bfloat16_as_ushort(lx1) << 16) | __bfloat16_as_ushort(lx0);
        *(uint32_t*)&g_Chi[i1] = ((uint32_t)__bfloat16_as_ushort(hy1) << 16) | __bfloat16_as_ushort(hy0);
        *(uint32_t*)&g_Clo[i1] = ((uint32_t)__bfloat16_as_ushort(ly1) << 16) | __bfloat16_as_ushort(ly0);
    }
}

// ---------------------------------------------------------------------------
extern "C" void kernel_launch(void* const* d_in, const int* in_sizes, int n_in,
                              void* d_out, int out_size)
{
    const float* Xq = (const float*)d_in[0];
    const float* Xk = (const float*)d_in[1];
    const float* Xv = (const float*)d_in[2];
    const float* Wq = (const float*)d_in[3];
    const float* bq = (const float*)d_in[4];
    const float* Wk = (const float*)d_in[5];
    const float* bk = (const float*)d_in[6];
    const float* Wv = (const float*)d_in[7];
    const float* bv = (const float*)d_in[8];
    const float* Wo = (const float*)d_in[9];
    const float* bo = (const float*)d_in[10];
    float* out = (float*)d_out;

    cudaFuncSetAttribute(gemm_bf16,
                         cudaFuncAttributeMaxDynamicSharedMemorySize,
                         GEMM_SMEM_BYTES);
    cudaFuncSetAttribute(attn_mma,
                         cudaFuncAttributeMaxDynamicSharedMemorySize,
                         ATTN_SMEM_BYTES);

    prep<<<dim3(1024, 1, 7), 256>>>(Wq, Wk, Wv, Wo, Xq, Xk, Xv);

    dim3 gq(DM/64, MROWS/128, 3);    // fused QKV: 16 x 32 x 3
    gemm_bf16<<<gq, 256, GEMM_SMEM_BYTES>>>(1, bq, bk, bv, nullptr);

    dim3 ga(SEQ/128, BATCH*NH);      // 16 x 32
    attn_mma<<<ga, 256, ATTN_SMEM_BYTES>>>();

    dim3 gp(DM/64, MROWS/128, 1);    // out projection
    gemm_bf16<<<gp, 256, GEMM_SMEM_BYTES>>>(0, bo, bo, bo, out);
}

// round 10
// speedup vs baseline: 1.9495x; 1.5735x over previous
#include <cuda_runtime.h>
#include <cuda_fp16.h>
#include <cstdint>

#define DM   1024
#define NH   16
#define DK   64
#define BATCH 2
#define SEQ  2048
#define MROWS (BATCH*SEQ)   // 4096
#define NW   (DM*DM)
#define NX   (MROWS*DM)
#define NHD  (BATCH*NH*SEQ*DK)

// Scratch (sanctioned __device__ globals)
__device__ __half g_Wf[4*NW];              // fp16 weights (Wq,Wk,Wv,Wo)
__device__ __half g_Xhi[3*NX], g_Xlo[3*NX]; // fp16 split inputs
__device__ __half g_Chi[NX],   g_Clo[NX];   // fp16 split ctx [b,s,h*d]
__device__ __half g_Qf[NHD];               // fp16 Q (prescaled) [b,h,s,d]
__device__ __half g_Kf[NHD];               // fp16 K [b,h,s,d]
__device__ __half g_Vf[NHD];               // fp16 V TRANSPOSED [b,h,d,s]

// ---------------------------------------------------------------------------
// helpers
// ---------------------------------------------------------------------------
__device__ __forceinline__ float ex2f(float x) {
    float y;
    asm("ex2.approx.f32 %0, %1;" : "=f"(y) : "f"(x));
    return y;
}
// pack two f32 -> fp16x2 (lo in low half: memory order [lo, hi])
__device__ __forceinline__ uint32_t packh2(float lo, float hi) {
    uint32_t u;
    asm("cvt.rn.f16x2.f32 %0, %1, %2;" : "=r"(u) : "f"(hi), "f"(lo));
    return u;
}
// fp16 m16n8k16 full-rate HMMA
__device__ __forceinline__ void mma_fp16(float* c, const uint32_t* a,
                                         uint32_t b0, uint32_t b1) {
    asm volatile(
        "mma.sync.aligned.m16n8k16.row.col.f32.f16.f16.f32 "
        "{%0,%1,%2,%3},{%4,%5,%6,%7},{%8,%9},{%0,%1,%2,%3};"
        : "+f"(c[0]), "+f"(c[1]), "+f"(c[2]), "+f"(c[3])
        : "r"(a[0]), "r"(a[1]), "r"(a[2]), "r"(a[3]), "r"(b0), "r"(b1));
}
__device__ __forceinline__ void cpa16(uint32_t dst, const void* src) {
    asm volatile("cp.async.cg.shared.global [%0], [%1], 16;\n"
                 :: "r"(dst), "l"(src));
}
#define CP_COMMIT() asm volatile("cp.async.commit_group;\n" ::: "memory")
#define CP_WAIT1()  asm volatile("cp.async.wait_group 1;\n" ::: "memory")

// ---------------------------------------------------------------------------
// prep: z 0-3 -> weights fp16 single; z 4-6 -> inputs fp16 hi/lo split.
// ---------------------------------------------------------------------------
__global__ __launch_bounds__(256)
void prep(const float* __restrict__ Wq, const float* __restrict__ Wk,
          const float* __restrict__ Wv, const float* __restrict__ Wo,
          const float* __restrict__ Xq, const float* __restrict__ Xk,
          const float* __restrict__ Xv)
{
    const int z = blockIdx.z;
    const float* src = (z==0)?Wq:(z==1)?Wk:(z==2)?Wv:(z==3)?Wo:
                       (z==4)?Xq:(z==5)?Xk:Xv;
    const int n4 = ((z < 4) ? NW : NX) >> 2;
    const int stride = gridDim.x * blockDim.x;
    if (z < 4) {
        __half* dw = g_Wf + (size_t)z*NW;
        for (int i = blockIdx.x*blockDim.x + threadIdx.x; i < n4; i += stride) {
            float4 v = ((const float4*)src)[i];
            uint2 u;
            u.x = packh2(v.x, v.y);
            u.y = packh2(v.z, v.w);
            *(uint2*)&dw[(size_t)i*4] = u;
        }
    } else {
        __half* dh = g_Xhi + (size_t)(z-4)*NX;
        __half* dl = g_Xlo + (size_t)(z-4)*NX;
        for (int i = blockIdx.x*blockDim.x + threadIdx.x; i < n4; i += stride) {
            float4 v = ((const float4*)src)[i];
            __half h0 = __float2half_rn(v.x);
            __half h1 = __float2half_rn(v.y);
            __half h2 = __float2half_rn(v.z);
            __half h3 = __float2half_rn(v.w);
            uint2 uh, ul;
            uh.x = ((uint32_t)__half_as_ushort(h1) << 16) | __half_as_ushort(h0);
            uh.y = ((uint32_t)__half_as_ushort(h3) << 16) | __half_as_ushort(h2);
            ul.x = packh2(v.x - __half2float(h0), v.y - __half2float(h1));
            ul.y = packh2(v.z - __half2float(h2), v.w - __half2float(h3));
            *(uint2*)&dh[(size_t)i*4] = uh;
            *(uint2*)&dl[(size_t)i*4] = ul;
        }
    }
}

// ---------------------------------------------------------------------------
// GEMM on mma.sync fp16 m16n8k16: A = Ahi+Alo (fp16 split), W single fp16,
// 2 products (AhW + AlW) into fp32 accumulator.
// Block 128m x 64n, K-chunk 64 (4 k16 slabs), 2-stage cp.async.
// 8 warps as 4m x 2n (warp tile 32x32). Pitch 36 u32 (fp16x2 pairs).
// mode=1: z picks Xq->Qf(prescaled), Xk->Kf, Xv->Vf(TRANSPOSED [b,h,d,s])
// mode=0: (ctx hi/lo, Wo) -> out fp32 + bias
// ---------------------------------------------------------------------------
#define PW 36
#define S_A (128*PW)                  // 4608 words per A operand
#define S_WN (64*PW)                  // 2304 words W
#define STG_WORDS (2*S_A + S_WN)      // 11520
#define AH_O 0
#define AL_O S_A
#define WW_O (2*S_A)
#define GEMM_SMEM_BYTES (2*STG_WORDS*4)   // 92160

__global__ __launch_bounds__(256, 2)
void gemm_fp16(int mode, const float* __restrict__ b0p,
               const float* __restrict__ b1p, const float* __restrict__ b2p,
               float* __restrict__ outp)
{
    extern __shared__ uint32_t gsm[];

    const int z = blockIdx.z;
    const __half* Ahi = mode ? (g_Xhi + (size_t)z*NX) : g_Chi;
    const __half* Alo = mode ? (g_Xlo + (size_t)z*NX) : g_Clo;
    const int wsel = mode ? z : 3;
    const __half* WG = g_Wf + (size_t)wsel*NW;
    const float* bias = mode ? ((z==0)?b0p:(z==1)?b1p:b2p) : b0p;

    const int m0 = blockIdx.y * 128;
    const int n0 = blockIdx.x * 64;
    const int tid = threadIdx.x;
    const int w = tid >> 5;
    const int lane = tid & 31;
    const int g = lane >> 2, tg = lane & 3;
    const int wm = w & 3;
    const int wn = w >> 2;

    const uint32_t sbase = (uint32_t)__cvta_generic_to_shared(gsm);

    auto stage = [&](int kc, int s) {
        int k0 = kc * 64;
        uint32_t bb = sbase + (uint32_t)(s * STG_WORDS) * 4u;
        // A hi/lo: 128 rows x 8 granules(16B=8 fp16) = 1024 each, 4/thread
#pragma unroll
        for (int i = 0; i < 4; i++) {
            int f = tid + i*256;
            int r = f >> 3, ch = f & 7;
            uint32_t d = bb + (uint32_t)(r*PW + ch*4)*4u;
            size_t so = (size_t)(m0 + r)*DM + k0 + ch*8;
            cpa16(d + AH_O*4u, Ahi + so);
            cpa16(d + AL_O*4u, Alo + so);
        }
        // W: 64 rows x 8 = 512 granules, 2/thread
#pragma unroll
        for (int i = 0; i < 2; i++) {
            int f = tid + i*256;
            int r = f >> 3, ch = f & 7;
            uint32_t d = bb + (uint32_t)(r*PW + ch*4)*4u;
            cpa16(d + WW_O*4u, WG + (size_t)(n0 + r)*DM + k0 + ch*8);
        }
    };

    float acc[2][4][4];
#pragma unroll
    for (int mi = 0; mi < 2; mi++)
#pragma unroll
        for (int nt = 0; nt < 4; nt++)
#pragma unroll
            for (int j = 0; j < 4; j++) acc[mi][nt][j] = 0.f;

    stage(0, 0); CP_COMMIT();
    stage(1, 1); CP_COMMIT();

    const int NCH = DM/64;   // 16
    for (int kc = 0; kc < NCH; kc++) {
        CP_WAIT1();
        __syncthreads();

        uint32_t* Sh = gsm + (kc & 1) * STG_WORDS;
        uint32_t* Ah = Sh + AH_O;
        uint32_t* Al = Sh + AL_O;
        uint32_t* Wf = Sh + WW_O;

#pragma unroll
        for (int ks = 0; ks < 4; ks++) {
            int c = ks*8 + tg;
            uint32_t afh[2][4], afl[2][4];
#pragma unroll
            for (int mi = 0; mi < 2; mi++) {
                int ar = (wm*32 + mi*16 + g)*PW + c;
                afh[mi][0] = Ah[ar];
                afh[mi][1] = Ah[ar + 8*PW];
                afh[mi][2] = Ah[ar + 4];
                afh[mi][3] = Ah[ar + 8*PW + 4];
                afl[mi][0] = Al[ar];
                afl[mi][1] = Al[ar + 8*PW];
                afl[mi][2] = Al[ar + 4];
                afl[mi][3] = Al[ar + 8*PW + 4];
            }
#pragma unroll
            for (int nt = 0; nt < 4; nt++) {
                int ka = (wn*32 + nt*8 + g)*PW + c;
                uint32_t b0 = Wf[ka], b1 = Wf[ka + 4];
#pragma unroll
                for (int mi = 0; mi < 2; mi++) {
                    mma_fp16(acc[mi][nt], afh[mi], b0, b1);
                    mma_fp16(acc[mi][nt], afl[mi], b0, b1);
                }
            }
        }
        __syncthreads();

        if (kc + 2 < NCH) stage(kc + 2, kc & 1);
        CP_COMMIT();
    }

    // epilogue
    const float QSCALE = 0.125f * 1.4426950408889634f;
    const int h = blockIdx.x;
#pragma unroll
    for (int nt = 0; nt < 4; nt++) {
        int nc = wn*32 + nt*8 + 2*tg;
        float bb0 = bias[n0 + nc], bb1 = bias[n0 + nc + 1];
#pragma unroll
        for (int mi = 0; mi < 2; mi++) {
            int mA = m0 + wm*32 + mi*16 + g;
            int mB = mA + 8;
            float x0 = acc[mi][nt][0] + bb0, x1 = acc[mi][nt][1] + bb1;
            float y0 = acc[mi][nt][2] + bb0, y1 = acc[mi][nt][3] + bb1;
            if (mode) {
                int bA = mA >> 11, sA = mA & (SEQ-1);
                int sB = sA + 8;
                if (z == 2) {
                    // V transposed [b,h,d,s]
                    size_t vb = ((size_t)(bA*NH + h)) * DK;
                    g_Vf[(vb + nc  )*SEQ + sA] = __float2half_rn(x0);
                    g_Vf[(vb + nc+1)*SEQ + sA] = __float2half_rn(x1);
                    g_Vf[(vb + nc  )*SEQ + sB] = __float2half_rn(y0);
                    g_Vf[(vb + nc+1)*SEQ + sB] = __float2half_rn(y1);
                } else {
                    __half* dst = (z == 0) ? g_Qf : g_Kf;
                    float sc = (z == 0) ? QSCALE : 1.0f;
                    size_t oA = (((size_t)(bA*NH + h)) * SEQ + sA) * DK + nc;
                    size_t oB = (((size_t)(bA*NH + h)) * SEQ + sB) * DK + nc;
                    *(uint32_t*)&dst[oA] = packh2(x0*sc, x1*sc);
                    *(uint32_t*)&dst[oB] = packh2(y0*sc, y1*sc);
                }
            } else {
                *(float2*)&outp[(size_t)mA * DM + n0 + nc] = make_float2(x0, x1);
                *(float2*)&outp[(size_t)mB * DM + n0 + nc] = make_float2(y0, y1);
            }
        }
    }
}

// ---------------------------------------------------------------------------
// Flash attention on fp16 m16n8k16. q-tile 128, kv-tile 64, 8 warps
// (warp = 16 rows). cp.async double-buffered K/V. P repack is pure register
// packing (C-frag cols == A-frag cols for k16). V stored [b,h,d,s] so PV
// B-frags are natural u32 reads. Softmax log2-domain (Q prescaled).
// smem: Qs 128x36 | Ks[2] 64x36 | Vs[2] 64x36 (u32 words) = 55296 B.
// ---------------------------------------------------------------------------
#define AQ_SZ (128*PW)
#define AK_SZ (64*PW)
#define ATTN_SMEM_BYTES ((AQ_SZ + 4*AK_SZ)*4)   // 55296

__global__ __launch_bounds__(256, 2)
void attn_fp16()
{
    extern __shared__ uint32_t sm[];
    uint32_t* Qs = sm;
    uint32_t* KsB[2] = { sm + AQ_SZ, sm + AQ_SZ + AK_SZ };
    uint32_t* VsB[2] = { sm + AQ_SZ + 2*AK_SZ, sm + AQ_SZ + 3*AK_SZ };

    const int bh = blockIdx.y;
    const int q0 = blockIdx.x * 128;
    const size_t base = (size_t)bh * SEQ * DK;     // [b,h,s,d] for Q/K
    const size_t vbase = (size_t)bh * DK * SEQ;    // [b,h,d,s] for V
    const int tid = threadIdx.x;
    const int w = tid >> 5;
    const int lane = tid & 31;
    const int g = lane >> 2, tg = lane & 3;

    const uint32_t sbase = (uint32_t)__cvta_generic_to_shared(sm);

    auto stageKV = [&](int t, int b) {
        int s0 = t * 64;
        uint32_t kB = sbase + ((AQ_SZ + (b ? AK_SZ : 0)) << 2);
        uint32_t vB = sbase + ((AQ_SZ + 2*AK_SZ + (b ? AK_SZ : 0)) << 2);
        // K: 64 rows(s) x 8 granules; V: 64 rows(d) x 8 granules; 2/thread each
#pragma unroll
        for (int i = 0; i < 2; i++) {
            int f = tid + i*256;
            int r = f >> 3, ch = f & 7;
            uint32_t off = (uint32_t)(r*PW + ch*4)*4u;
            cpa16(kB + off, g_Kf + base + (size_t)(s0 + r)*DK + ch*8);
            cpa16(vB + off, g_Vf + vbase + (size_t)r*SEQ + s0 + ch*8);
        }
    };

    // prologue: Q (128 rows x 8 granules = 1024, 4/thread) + tile0
#pragma unroll
    for (int i = 0; i < 4; i++) {
        int f = tid + i*256;
        int r = f >> 3, ch = f & 7;
        cpa16(sbase + (uint32_t)(r*PW + ch*4)*4u,
              g_Qf + base + (size_t)(q0 + r)*DK + ch*8);
    }
    stageKV(0, 0);
    CP_COMMIT();

    const int pr0 = (w*16 + g) * PW;
    const int pr1 = pr0 + 8 * PW;

    float of[8][4];
#pragma unroll
    for (int dt = 0; dt < 8; dt++)
#pragma unroll
        for (int j = 0; j < 4; j++) of[dt][j] = 0.f;
    float m0 = -1e30f, m1 = -1e30f, l0 = 0.f, l1 = 0.f;

    const int NT = SEQ/64;
    for (int t = 0; t < NT; t++) {
        if (t + 1 < NT) stageKV(t + 1, (t + 1) & 1);
        CP_COMMIT();
        CP_WAIT1();
        __syncthreads();

        uint32_t* Ks = KsB[t & 1];
        uint32_t* Vs = VsB[t & 1];

        // S = Q . K^T : 4 k16 slabs x 8 n-tiles
        float sacc[8][4];
#pragma unroll
        for (int nt = 0; nt < 8; nt++)
#pragma unroll
            for (int j = 0; j < 4; j++) sacc[nt][j] = 0.f;
#pragma unroll
        for (int ks = 0; ks < 4; ks++) {
            int c = ks*8 + tg;
            uint32_t qf[4];
            qf[0] = Qs[pr0 + c];
            qf[1] = Qs[pr1 + c];
            qf[2] = Qs[pr0 + c + 4];
            qf[3] = Qs[pr1 + c + 4];
#pragma unroll
            for (int nt = 0; nt < 8; nt++) {
                int ka = (nt*8 + g)*PW + c;
                mma_fp16(sacc[nt], qf, Ks[ka], Ks[ka + 4]);
            }
        }

        // online softmax (rows g, g+8; reduce over tg lanes); log2 domain
        float tm0 = -1e30f, tm1 = -1e30f;
#pragma unroll
        for (int nt = 0; nt < 8; nt++) {
            tm0 = fmaxf(tm0, fmaxf(sacc[nt][0], sacc[nt][1]));
            tm1 = fmaxf(tm1, fmaxf(sacc[nt][2], sacc[nt][3]));
        }
        tm0 = fmaxf(tm0, __shfl_xor_sync(0xffffffffu, tm0, 1));
        tm0 = fmaxf(tm0, __shfl_xor_sync(0xffffffffu, tm0, 2));
        tm1 = fmaxf(tm1, __shfl_xor_sync(0xffffffffu, tm1, 1));
        tm1 = fmaxf(tm1, __shfl_xor_sync(0xffffffffu, tm1, 2));

        float mn0 = fmaxf(m0, tm0), mn1 = fmaxf(m1, tm1);
        float a0 = ex2f(m0 - mn0), a1 = ex2f(m1 - mn1);
        m0 = mn0; m1 = mn1;

        float rs0 = 0.f, rs1 = 0.f;
#pragma unroll
        for (int nt = 0; nt < 8; nt++) {
            float p0 = ex2f(sacc[nt][0] - mn0);
            float p1 = ex2f(sacc[nt][1] - mn0);
            float p2 = ex2f(sacc[nt][2] - mn1);
            float p3 = ex2f(sacc[nt][3] - mn1);
            sacc[nt][0] = p0; sacc[nt][1] = p1;
            sacc[nt][2] = p2; sacc[nt][3] = p3;
            rs0 += p0 + p1;
            rs1 += p2 + p3;
        }
        rs0 += __shfl_xor_sync(0xffffffffu, rs0, 1);
        rs0 += __shfl_xor_sync(0xffffffffu, rs0, 2);
        rs1 += __shfl_xor_sync(0xffffffffu, rs1, 1);
        rs1 += __shfl_xor_sync(0xffffffffu, rs1, 2);
        l0 = l0 * a0 + rs0;
        l1 = l1 * a1 + rs1;
#pragma unroll
        for (int dt = 0; dt < 8; dt++) {
            of[dt][0] *= a0; of[dt][1] *= a0;
            of[dt][2] *= a1; of[dt][3] *= a1;
        }

        // O += P . V : P C-frag -> A-frag is pure register packing (no shfl)
#pragma unroll
        for (int ks = 0; ks < 4; ks++) {
            uint32_t pa[4];
            pa[0] = packh2(sacc[2*ks  ][0], sacc[2*ks  ][1]);
            pa[1] = packh2(sacc[2*ks  ][2], sacc[2*ks  ][3]);
            pa[2] = packh2(sacc[2*ks+1][0], sacc[2*ks+1][1]);
            pa[3] = packh2(sacc[2*ks+1][2], sacc[2*ks+1][3]);
            int c = ks*8 + tg;
#pragma unroll
            for (int dt = 0; dt < 8; dt++) {
                int va = (dt*8 + g)*PW + c;
                mma_fp16(of[dt], pa, Vs[va], Vs[va + 4]);
            }
        }
        __syncthreads();
    }

    // epilogue: normalize -> fp16 hi/lo ctx, [b, s, h, d] concat layout
    float inv0 = 1.0f / l0, inv1 = 1.0f / l1;
    const int b = bh >> 4, h = bh & 15;
    const int sg0 = q0 + w*16 + g, sg1 = sg0 + 8;
#pragma unroll
    for (int dt = 0; dt < 8; dt++) {
        int dcol = dt*8 + 2*tg;
        size_t i0 = ((size_t)(b*SEQ + sg0) * NH + h) * DK + dcol;
        size_t i1 = ((size_t)(b*SEQ + sg1) * NH + h) * DK + dcol;
        float x0 = of[dt][0]*inv0, x1 = of[dt][1]*inv0;
        float y0 = of[dt][2]*inv1, y1 = of[dt][3]*inv1;
        __half hx0 = __float2half_rn(x0);
        __half hx1 = __float2half_rn(x1);
        __half hy0 = __float2half_rn(y0);
        __half hy1 = __float2half_rn(y1);
        *(uint32_t*)&g_Chi[i0] = ((uint32_t)__half_as_ushort(hx1) << 16) | __half_as_ushort(hx0);
        *(uint32_t*)&g_Chi[i1] = ((uint32_t)__half_as_ushort(hy1) << 16) | __half_as_ushort(hy0);
        *(uint32_t*)&g_Clo[i0] = packh2(x0 - __half2float(hx0), x1 - __half2float(hx1));
        *(uint32_t*)&g_Clo[i1] = packh2(y0 - __half2float(hy0), y1 - __half2float(hy1));
    }
}

// ---------------------------------------------------------------------------
extern "C" void kernel_launch(void* const* d_in, const int* in_sizes, int n_in,
                              void* d_out, int out_size)
{
    const float* Xq = (const float*)d_in[0];
    const float* Xk = (const float*)d_in[1];
    const float* Xv = (const float*)d_in[2];
    const float* Wq = (const float*)d_in[3];
    const float* bq = (const float*)d_in[4];
    const float* Wk = (const float*)d_in[5];
    const float* bk = (const float*)d_in[6];
    const float* Wv = (const float*)d_in[7];
    const float* bv = (const float*)d_in[8];
    const float* Wo = (const float*)d_in[9];
    const float* bo = (const float*)d_in[10];
    float* out = (float*)d_out;

    cudaFuncSetAttribute(gemm_fp16,
                         cudaFuncAttributeMaxDynamicSharedMemorySize,
                         GEMM_SMEM_BYTES);
    cudaFuncSetAttribute(attn_fp16,
                         cudaFuncAttributeMaxDynamicSharedMemorySize,
                         ATTN_SMEM_BYTES);

    prep<<<dim3(1024, 1, 7), 256>>>(Wq, Wk, Wv, Wo, Xq, Xk, Xv);

    dim3 gq(DM/64, MROWS/128, 3);    // fused QKV: 16 x 32 x 3
    gemm_fp16<<<gq, 256, GEMM_SMEM_BYTES>>>(1, bq, bk, bv, nullptr);

    dim3 ga(SEQ/128, BATCH*NH);      // 16 x 32
    attn_fp16<<<ga, 256, ATTN_SMEM_BYTES>>>();

    dim3 gp(DM/64, MROWS/128, 1);    // out projection
    gemm_fp16<<<gp, 256, GEMM_SMEM_BYTES>>>(0, bo, bo, bo, out);
}

// round 11
// speedup vs baseline: 2.2539x; 1.1562x over previous
#include <cuda_runtime.h>
#include <cuda_fp16.h>
#include <cstdint>

#define DM   1024
#define NH   16
#define DK   64
#define BATCH 2
#define SEQ  2048
#define MROWS (BATCH*SEQ)   // 4096
#define NW   (DM*DM)
#define NX   (MROWS*DM)
#define NHD  (BATCH*NH*SEQ*DK)

// Scratch (sanctioned __device__ globals)
__device__ __half g_Wf[4*NW];               // fp16 weights (Wq,Wk,Wv,Wo)
__device__ __half g_Xhi[3*NX], g_Xlo[3*NX]; // fp16 split inputs
__device__ __half g_Chi[NX],   g_Clo[NX];   // fp16 split ctx [b,s,h*d]
__device__ __half g_Qf[NHD];                // fp16 Q (prescaled) [b,h,s,d]
__device__ __half g_Kf[NHD];                // fp16 K [b,h,s,d]
__device__ __half g_Vf[NHD];                // fp16 V TRANSPOSED [b,h,d,s]

// ---------------------------------------------------------------------------
// helpers
// ---------------------------------------------------------------------------
__device__ __forceinline__ float ex2f(float x) {
    float y;
    asm("ex2.approx.f32 %0, %1;" : "=f"(y) : "f"(x));
    return y;
}
__device__ __forceinline__ uint32_t packh2(float lo, float hi) {
    uint32_t u;
    asm("cvt.rn.f16x2.f32 %0, %1, %2;" : "=r"(u) : "f"(hi), "f"(lo));
    return u;
}
__device__ __forceinline__ void mma_fp16(float* c, const uint32_t* a,
                                         uint32_t b0, uint32_t b1) {
    asm volatile(
        "mma.sync.aligned.m16n8k16.row.col.f32.f16.f16.f32 "
        "{%0,%1,%2,%3},{%4,%5,%6,%7},{%8,%9},{%0,%1,%2,%3};"
        : "+f"(c[0]), "+f"(c[1]), "+f"(c[2]), "+f"(c[3])
        : "r"(a[0]), "r"(a[1]), "r"(a[2]), "r"(a[3]), "r"(b0), "r"(b1));
}
// ldmatrix x4: four 8x8 b16 matrices; lane group j supplies rows of matrix j
__device__ __forceinline__ void ldsm4(uint32_t* r, uint32_t addr) {
    asm volatile("ldmatrix.sync.aligned.m8n8.x4.shared.b16 {%0,%1,%2,%3}, [%4];"
        : "=r"(r[0]), "=r"(r[1]), "=r"(r[2]), "=r"(r[3]) : "r"(addr));
}
__device__ __forceinline__ void cpa16(uint32_t dst, const void* src) {
    asm volatile("cp.async.cg.shared.global [%0], [%1], 16;\n"
                 :: "r"(dst), "l"(src));
}
#define CP_COMMIT() asm volatile("cp.async.commit_group;\n" ::: "memory")
#define CP_WAIT1()  asm volatile("cp.async.wait_group 1;\n" ::: "memory")

// ---------------------------------------------------------------------------
// prep: z 0-3 -> weights fp16 single; z 4-6 -> inputs fp16 hi/lo split.
// ---------------------------------------------------------------------------
__global__ __launch_bounds__(256)
void prep(const float* __restrict__ Wq, const float* __restrict__ Wk,
          const float* __restrict__ Wv, const float* __restrict__ Wo,
          const float* __restrict__ Xq, const float* __restrict__ Xk,
          const float* __restrict__ Xv)
{
    const int z = blockIdx.z;
    const float* src = (z==0)?Wq:(z==1)?Wk:(z==2)?Wv:(z==3)?Wo:
                       (z==4)?Xq:(z==5)?Xk:Xv;
    const int n4 = ((z < 4) ? NW : NX) >> 2;
    const int stride = gridDim.x * blockDim.x;
    if (z < 4) {
        __half* dw = g_Wf + (size_t)z*NW;
        for (int i = blockIdx.x*blockDim.x + threadIdx.x; i < n4; i += stride) {
            float4 v = ((const float4*)src)[i];
            uint2 u;
            u.x = packh2(v.x, v.y);
            u.y = packh2(v.z, v.w);
            *(uint2*)&dw[(size_t)i*4] = u;
        }
    } else {
        __half* dh = g_Xhi + (size_t)(z-4)*NX;
        __half* dl = g_Xlo + (size_t)(z-4)*NX;
        for (int i = blockIdx.x*blockDim.x + threadIdx.x; i < n4; i += stride) {
            float4 v = ((const float4*)src)[i];
            __half h0 = __float2half_rn(v.x);
            __half h1 = __float2half_rn(v.y);
            __half h2 = __float2half_rn(v.z);
            __half h3 = __float2half_rn(v.w);
            uint2 uh, ul;
            uh.x = ((uint32_t)__half_as_ushort(h1) << 16) | __half_as_ushort(h0);
            uh.y = ((uint32_t)__half_as_ushort(h3) << 16) | __half_as_ushort(h2);
            ul.x = packh2(v.x - __half2float(h0), v.y - __half2float(h1));
            ul.y = packh2(v.z - __half2float(h2), v.w - __half2float(h3));
            *(uint2*)&dh[(size_t)i*4] = uh;
            *(uint2*)&dl[(size_t)i*4] = ul;
        }
    }
}

// ---------------------------------------------------------------------------
// GEMM on mma.sync fp16 m16n8k16 + ldmatrix fragments.
// A = Ahi+Alo (fp16 split), W single fp16, 2 products into fp32 acc.
// Block 128m x 64n, K-chunk 64 (4 k16 slabs), 2-stage cp.async.
// 8 warps as 4m x 2n (warp tile 32x32). Pitch 36 u32 (LDSM conflict-free).
// ---------------------------------------------------------------------------
#define PW 36
#define S_A (128*PW)
#define S_WN (64*PW)
#define STG_WORDS (2*S_A + S_WN)      // 11520
#define GEMM_SMEM_BYTES (2*STG_WORDS*4)   // 92160

__global__ __launch_bounds__(256, 2)
void gemm_fp16(int mode, const float* __restrict__ b0p,
               const float* __restrict__ b1p, const float* __restrict__ b2p,
               float* __restrict__ outp)
{
    extern __shared__ uint32_t gsm[];

    const int z = blockIdx.z;
    const __half* Ahi = mode ? (g_Xhi + (size_t)z*NX) : g_Chi;
    const __half* Alo = mode ? (g_Xlo + (size_t)z*NX) : g_Clo;
    const int wsel = mode ? z : 3;
    const __half* WG = g_Wf + (size_t)wsel*NW;
    const float* bias = mode ? ((z==0)?b0p:(z==1)?b1p:b2p) : b0p;

    const int m0 = blockIdx.y * 128;
    const int n0 = blockIdx.x * 64;
    const int tid = threadIdx.x;
    const int w = tid >> 5;
    const int lane = tid & 31;
    const int g = lane >> 2, tg = lane & 3;
    const int wm = w & 3;
    const int wn = w >> 2;

    const uint32_t sbase = (uint32_t)__cvta_generic_to_shared(gsm);

    // LDSM lane addressing (words within tile), rows conflict-free (pitch 36)
    // A (m16k16 x4): row = base + (l&7) + ((l>>3)&1)*8 ; khalf = l>>4
    const uint32_t aOffW = (uint32_t)((wm*32 + (lane&7) + ((lane>>3)&1)*8)*PW
                                      + (lane>>4)*4);
    // W (two n8k16 tiles per x4): n_row = base + ((l>>4)&1)*8 + (l&7) ; khalf = (l>>3)&1
    const uint32_t wOffW = (uint32_t)((wn*32 + ((lane>>4)&1)*8 + (lane&7))*PW
                                      + ((lane>>3)&1)*4);

    auto stage = [&](int kc, int s) {
        int k0 = kc * 64;
        uint32_t bb = sbase + (uint32_t)(s * STG_WORDS) * 4u;
#pragma unroll
        for (int i = 0; i < 4; i++) {
            int f = tid + i*256;
            int r = f >> 3, ch = f & 7;
            uint32_t d = bb + (uint32_t)(r*PW + ch*4)*4u;
            size_t so = (size_t)(m0 + r)*DM + k0 + ch*8;
            cpa16(d, Ahi + so);
            cpa16(d + S_A*4u, Alo + so);
        }
#pragma unroll
        for (int i = 0; i < 2; i++) {
            int f = tid + i*256;
            int r = f >> 3, ch = f & 7;
            uint32_t d = bb + (uint32_t)(r*PW + ch*4)*4u;
            cpa16(d + 2*S_A*4u, WG + (size_t)(n0 + r)*DM + k0 + ch*8);
        }
    };

    float acc[2][4][4];
#pragma unroll
    for (int mi = 0; mi < 2; mi++)
#pragma unroll
        for (int nt = 0; nt < 4; nt++)
#pragma unroll
            for (int j = 0; j < 4; j++) acc[mi][nt][j] = 0.f;

    stage(0, 0); CP_COMMIT();
    stage(1, 1); CP_COMMIT();

    const int NCH = DM/64;   // 16
    for (int kc = 0; kc < NCH; kc++) {
        CP_WAIT1();
        __syncthreads();

        uint32_t bb = sbase + (uint32_t)((kc & 1) * STG_WORDS) * 4u;
        uint32_t aH = bb + aOffW*4u;
        uint32_t aL = aH + S_A*4u;
        uint32_t wB = bb + 2*S_A*4u + wOffW*4u;

#pragma unroll
        for (int ks = 0; ks < 4; ks++) {
            uint32_t off = (uint32_t)(ks*8)*4u;
            uint32_t afh[2][4], afl[2][4], wb[2][4];
            ldsm4(afh[0], aH + off);
            ldsm4(afh[1], aH + (uint32_t)(16*PW)*4u + off);
            ldsm4(afl[0], aL + off);
            ldsm4(afl[1], aL + (uint32_t)(16*PW)*4u + off);
            ldsm4(wb[0], wB + off);                            // nt0, nt1
            ldsm4(wb[1], wB + (uint32_t)(16*PW)*4u + off);     // nt2, nt3
#pragma unroll
            for (int p = 0; p < 2; p++) {
#pragma unroll
                for (int q = 0; q < 2; q++) {
                    uint32_t b0 = wb[p][q*2], b1 = wb[p][q*2+1];
                    int nt = p*2 + q;
#pragma unroll
                    for (int mi = 0; mi < 2; mi++) {
                        mma_fp16(acc[mi][nt], afh[mi], b0, b1);
                        mma_fp16(acc[mi][nt], afl[mi], b0, b1);
                    }
                }
            }
        }
        __syncthreads();

        if (kc + 2 < NCH) stage(kc + 2, kc & 1);
        CP_COMMIT();
    }

    // epilogue
    const float QSCALE = 0.125f * 1.4426950408889634f;
    const int h = blockIdx.x;
#pragma unroll
    for (int nt = 0; nt < 4; nt++) {
        int nc = wn*32 + nt*8 + 2*tg;
        float bb0 = bias[n0 + nc], bb1 = bias[n0 + nc + 1];
#pragma unroll
        for (int mi = 0; mi < 2; mi++) {
            int mA = m0 + wm*32 + mi*16 + g;
            int mB = mA + 8;
            float x0 = acc[mi][nt][0] + bb0, x1 = acc[mi][nt][1] + bb1;
            float y0 = acc[mi][nt][2] + bb0, y1 = acc[mi][nt][3] + bb1;
            if (mode) {
                int bA = mA >> 11, sA = mA & (SEQ-1);
                int sB = sA + 8;
                if (z == 2) {
                    size_t vb = ((size_t)(bA*NH + h)) * DK;
                    g_Vf[(vb + nc  )*SEQ + sA] = __float2half_rn(x0);
                    g_Vf[(vb + nc+1)*SEQ + sA] = __float2half_rn(x1);
                    g_Vf[(vb + nc  )*SEQ + sB] = __float2half_rn(y0);
                    g_Vf[(vb + nc+1)*SEQ + sB] = __float2half_rn(y1);
                } else {
                    __half* dst = (z == 0) ? g_Qf : g_Kf;
                    float sc = (z == 0) ? QSCALE : 1.0f;
                    size_t oA = (((size_t)(bA*NH + h)) * SEQ + sA) * DK + nc;
                    size_t oB = (((size_t)(bA*NH + h)) * SEQ + sB) * DK + nc;
                    *(uint32_t*)&dst[oA] = packh2(x0*sc, x1*sc);
                    *(uint32_t*)&dst[oB] = packh2(y0*sc, y1*sc);
                }
            } else {
                *(float2*)&outp[(size_t)mA * DM + n0 + nc] = make_float2(x0, x1);
                *(float2*)&outp[(size_t)mB * DM + n0 + nc] = make_float2(y0, y1);
            }
        }
    }
}

// ---------------------------------------------------------------------------
// Flash attention on fp16 m16n8k16 + ldmatrix fragments.
// q-tile 128, kv-tile 64, 8 warps. cp.async double-buffered K/V.
// P repack is pure register packing. V stored [b,h,d,s].
// ---------------------------------------------------------------------------
#define AQ_SZ (128*PW)
#define AK_SZ (64*PW)
#define ATTN_SMEM_BYTES ((AQ_SZ + 4*AK_SZ)*4)   // 55296

__global__ __launch_bounds__(256, 2)
void attn_fp16()
{
    extern __shared__ uint32_t sm[];

    const int bh = blockIdx.y;
    const int q0 = blockIdx.x * 128;
    const size_t base = (size_t)bh * SEQ * DK;     // [b,h,s,d] Q/K
    const size_t vbase = (size_t)bh * DK * SEQ;    // [b,h,d,s] V
    const int tid = threadIdx.x;
    const int w = tid >> 5;
    const int lane = tid & 31;
    const int g = lane >> 2, tg = lane & 3;

    const uint32_t sbase = (uint32_t)__cvta_generic_to_shared(sm);

    // LDSM lane addressing (words)
    const uint32_t qOffW = (uint32_t)((w*16 + (lane&7) + ((lane>>3)&1)*8)*PW
                                      + (lane>>4)*4);
    const uint32_t bOffW = (uint32_t)((((lane>>4)&1)*8 + (lane&7))*PW
                                      + ((lane>>3)&1)*4);   // K/V two-tile x4

    auto stageKV = [&](int t, int b) {
        int s0 = t * 64;
        uint32_t kB = sbase + ((AQ_SZ + (b ? AK_SZ : 0)) << 2);
        uint32_t vB = sbase + ((AQ_SZ + 2*AK_SZ + (b ? AK_SZ : 0)) << 2);
#pragma unroll
        for (int i = 0; i < 2; i++) {
            int f = tid + i*256;
            int r = f >> 3, ch = f & 7;
            uint32_t off = (uint32_t)(r*PW + ch*4)*4u;
            cpa16(kB + off, g_Kf + base + (size_t)(s0 + r)*DK + ch*8);
            cpa16(vB + off, g_Vf + vbase + (size_t)r*SEQ + s0 + ch*8);
        }
    };

#pragma unroll
    for (int i = 0; i < 4; i++) {
        int f = tid + i*256;
        int r = f >> 3, ch = f & 7;
        cpa16(sbase + (uint32_t)(r*PW + ch*4)*4u,
              g_Qf + base + (size_t)(q0 + r)*DK + ch*8);
    }
    stageKV(0, 0);
    CP_COMMIT();

    float of[8][4];
#pragma unroll
    for (int dt = 0; dt < 8; dt++)
#pragma unroll
        for (int j = 0; j < 4; j++) of[dt][j] = 0.f;
    float m0 = -1e30f, m1 = -1e30f, l0 = 0.f, l1 = 0.f;

    const int NT = SEQ/64;
    for (int t = 0; t < NT; t++) {
        if (t + 1 < NT) stageKV(t + 1, (t + 1) & 1);
        CP_COMMIT();
        CP_WAIT1();
        __syncthreads();

        const int b = t & 1;
        uint32_t qA = sbase + qOffW*4u;
        uint32_t kA = sbase + ((AQ_SZ + (b ? AK_SZ : 0)) << 2) + bOffW*4u;
        uint32_t vA = sbase + ((AQ_SZ + 2*AK_SZ + (b ? AK_SZ : 0)) << 2) + bOffW*4u;

        // S = Q . K^T
        float sacc[8][4];
#pragma unroll
        for (int nt = 0; nt < 8; nt++)
#pragma unroll
            for (int j = 0; j < 4; j++) sacc[nt][j] = 0.f;
#pragma unroll
        for (int ks = 0; ks < 4; ks++) {
            uint32_t off = (uint32_t)(ks*8)*4u;
            uint32_t qf[4];
            ldsm4(qf, qA + off);
#pragma unroll
            for (int p = 0; p < 4; p++) {
                uint32_t kb[4];
                ldsm4(kb, kA + (uint32_t)(p*16*PW)*4u + off);
                mma_fp16(sacc[2*p],   qf, kb[0], kb[1]);
                mma_fp16(sacc[2*p+1], qf, kb[2], kb[3]);
            }
        }

        // online softmax (log2 domain)
        float tm0 = -1e30f, tm1 = -1e30f;
#pragma unroll
        for (int nt = 0; nt < 8; nt++) {
            tm0 = fmaxf(tm0, fmaxf(sacc[nt][0], sacc[nt][1]));
            tm1 = fmaxf(tm1, fmaxf(sacc[nt][2], sacc[nt][3]));
        }
        tm0 = fmaxf(tm0, __shfl_xor_sync(0xffffffffu, tm0, 1));
        tm0 = fmaxf(tm0, __shfl_xor_sync(0xffffffffu, tm0, 2));
        tm1 = fmaxf(tm1, __shfl_xor_sync(0xffffffffu, tm1, 1));
        tm1 = fmaxf(tm1, __shfl_xor_sync(0xffffffffu, tm1, 2));

        float mn0 = fmaxf(m0, tm0), mn1 = fmaxf(m1, tm1);
        float a0 = ex2f(m0 - mn0), a1 = ex2f(m1 - mn1);
        m0 = mn0; m1 = mn1;

        float rs0 = 0.f, rs1 = 0.f;
#pragma unroll
        for (int nt = 0; nt < 8; nt++) {
            float p0 = ex2f(sacc[nt][0] - mn0);
            float p1 = ex2f(sacc[nt][1] - mn0);
            float p2 = ex2f(sacc[nt][2] - mn1);
            float p3 = ex2f(sacc[nt][3] - mn1);
            sacc[nt][0] = p0; sacc[nt][1] = p1;
            sacc[nt][2] = p2; sacc[nt][3] = p3;
            rs0 += p0 + p1;
            rs1 += p2 + p3;
        }
        rs0 += __shfl_xor_sync(0xffffffffu, rs0, 1);
        rs0 += __shfl_xor_sync(0xffffffffu, rs0, 2);
        rs1 += __shfl_xor_sync(0xffffffffu, rs1, 1);
        rs1 += __shfl_xor_sync(0xffffffffu, rs1, 2);
        l0 = l0 * a0 + rs0;
        l1 = l1 * a1 + rs1;
#pragma unroll
        for (int dt = 0; dt < 8; dt++) {
            of[dt][0] *= a0; of[dt][1] *= a0;
            of[dt][2] *= a1; of[dt][3] *= a1;
        }

        // O += P . V
#pragma unroll
        for (int ks = 0; ks < 4; ks++) {
            uint32_t pa[4];
            pa[0] = packh2(sacc[2*ks  ][0], sacc[2*ks  ][1]);
            pa[1] = packh2(sacc[2*ks  ][2], sacc[2*ks  ][3]);
            pa[2] = packh2(sacc[2*ks+1][0], sacc[2*ks+1][1]);
            pa[3] = packh2(sacc[2*ks+1][2], sacc[2*ks+1][3]);
            uint32_t off = (uint32_t)(ks*8)*4u;
#pragma unroll
            for (int p = 0; p < 4; p++) {
                uint32_t vb[4];
                ldsm4(vb, vA + (uint32_t)(p*16*PW)*4u + off);
                mma_fp16(of[2*p],   pa, vb[0], vb[1]);
                mma_fp16(of[2*p+1], pa, vb[2], vb[3]);
            }
        }
        __syncthreads();
    }

    // epilogue: normalize -> fp16 hi/lo ctx, [b, s, h, d] concat layout
    float inv0 = 1.0f / l0, inv1 = 1.0f / l1;
    const int b = bh >> 4, h = bh & 15;
    const int sg0 = q0 + w*16 + g, sg1 = sg0 + 8;
#pragma unroll
    for (int dt = 0; dt < 8; dt++) {
        int dcol = dt*8 + 2*tg;
        size_t i0 = ((size_t)(b*SEQ + sg0) * NH + h) * DK + dcol;
        size_t i1 = ((size_t)(b*SEQ + sg1) * NH + h) * DK + dcol;
        float x0 = of[dt][0]*inv0, x1 = of[dt][1]*inv0;
        float y0 = of[dt][2]*inv1, y1 = of[dt][3]*inv1;
        __half hx0 = __float2half_rn(x0);
        __half hx1 = __float2half_rn(x1);
        __half hy0 = __float2half_rn(y0);
        __half hy1 = __float2half_rn(y1);
        *(uint32_t*)&g_Chi[i0] = ((uint32_t)__half_as_ushort(hx1) << 16) | __half_as_ushort(hx0);
        *(uint32_t*)&g_Chi[i1] = ((uint32_t)__half_as_ushort(hy1) << 16) | __half_as_ushort(hy0);
        *(uint32_t*)&g_Clo[i0] = packh2(x0 - __half2float(hx0), x1 - __half2float(hx1));
        *(uint32_t*)&g_Clo[i1] = packh2(y0 - __half2float(hy0), y1 - __half2float(hy1));
    }
}

// ---------------------------------------------------------------------------
extern "C" void kernel_launch(void* const* d_in, const int* in_sizes, int n_in,
                              void* d_out, int out_size)
{
    const float* Xq = (const float*)d_in[0];
    const float* Xk = (const float*)d_in[1];
    const float* Xv = (const float*)d_in[2];
    const float* Wq = (const float*)d_in[3];
    const float* bq = (const float*)d_in[4];
    const float* Wk = (const float*)d_in[5];
    const float* bk = (const float*)d_in[6];
    const float* Wv = (const float*)d_in[7];
    const float* bv = (const float*)d_in[8];
    const float* Wo = (const float*)d_in[9];
    const float* bo = (const float*)d_in[10];
    float* out = (float*)d_out;

    cudaFuncSetAttribute(gemm_fp16,
                         cudaFuncAttributeMaxDynamicSharedMemorySize,
                         GEMM_SMEM_BYTES);
    cudaFuncSetAttribute(attn_fp16,
                         cudaFuncAttributeMaxDynamicSharedMemorySize,
                         ATTN_SMEM_BYTES);

    prep<<<dim3(1024, 1, 7), 256>>>(Wq, Wk, Wv, Wo, Xq, Xk, Xv);

    dim3 gq(DM/64, MROWS/128, 3);    // fused QKV: 16 x 32 x 3
    gemm_fp16<<<gq, 256, GEMM_SMEM_BYTES>>>(1, bq, bk, bv, nullptr);

    dim3 ga(SEQ/128, BATCH*NH);      // 16 x 32
    attn_fp16<<<ga, 256, ATTN_SMEM_BYTES>>>();

    dim3 gp(DM/64, MROWS/128, 1);    // out projection
    gemm_fp16<<<gp, 256, GEMM_SMEM_BYTES>>>(0, bo, bo, bo, out);
}